// round 3
// baseline (speedup 1.0000x reference)
#include <cuda_runtime.h>
#include <math.h>

// Problem constants
#define DIMX   1024
#define HEADS  16
#define HD     64
#define WIN    5
#define BATCH  2
#define SEQ    2048
#define MTOK   (BATCH * SEQ)      // 4096 tokens
#define EPSLN  1e-5f

// ---------------------------------------------------------------------------
// Scratch (device globals: no runtime allocation allowed)
// ---------------------------------------------------------------------------
__device__ float g_qkv    [MTOK * 3 * DIMX];   // 50 MB
__device__ float g_attn   [MTOK * DIMX];
__device__ float g_attnout[MTOK * DIMX];
__device__ float g_x1     [MTOK * DIMX];
__device__ float g_h      [MTOK * 4 * DIMX];   // 67 MB
__device__ float g_mlp    [MTOK * DIMX];

// ---------------------------------------------------------------------------
// GEMM (NT): C[m,n] = sum_k A[m*K+k] * W[n*K+k] + bias[n], optional exact GELU
// Tile: 128x128x16, 256 threads, 8x8 per-thread microtile.
// ---------------------------------------------------------------------------
__device__ __forceinline__ float gelu_exact(float x) {
    return 0.5f * x * (1.0f + erff(x * 0.70710678118654752440f));
}

template <int DO_GELU>
__global__ __launch_bounds__(256, 2)
void gemm_nt_kernel(const float* __restrict__ A, const float* __restrict__ W,
                    const float* __restrict__ bias, float* __restrict__ C,
                    int M, int N, int K)
{
    __shared__ float As[16][128];
    __shared__ float Ws[16][128];

    const int tid = threadIdx.x;
    const int tx  = tid & 15;          // N direction (16 threads)
    const int ty  = tid >> 4;          // M direction (16 threads)
    const int m0  = blockIdx.y << 7;
    const int n0  = blockIdx.x << 7;

    // Global-load mapping: 128x16 tile = 512 float4, 2 per thread
    const int r0 = tid >> 2;           // rows 0..63
    const int c0 = (tid & 3) << 2;     // col offset 0,4,8,12
    const int r1 = r0 + 64;            // rows 64..127

    float acc[8][8];
#pragma unroll
    for (int i = 0; i < 8; i++)
#pragma unroll
        for (int j = 0; j < 8; j++) acc[i][j] = 0.0f;

    const float* Ap = A + (size_t)m0 * K;
    const float* Wp = W + (size_t)n0 * K;

    for (int k0 = 0; k0 < K; k0 += 16) {
        float4 av0 = *(const float4*)(Ap + (size_t)r0 * K + k0 + c0);
        float4 av1 = *(const float4*)(Ap + (size_t)r1 * K + k0 + c0);
        float4 wv0 = *(const float4*)(Wp + (size_t)r0 * K + k0 + c0);
        float4 wv1 = *(const float4*)(Wp + (size_t)r1 * K + k0 + c0);

        As[c0 + 0][r0] = av0.x; As[c0 + 1][r0] = av0.y;
        As[c0 + 2][r0] = av0.z; As[c0 + 3][r0] = av0.w;
        As[c0 + 0][r1] = av1.x; As[c0 + 1][r1] = av1.y;
        As[c0 + 2][r1] = av1.z; As[c0 + 3][r1] = av1.w;
        Ws[c0 + 0][r0] = wv0.x; Ws[c0 + 1][r0] = wv0.y;
        Ws[c0 + 2][r0] = wv0.z; Ws[c0 + 3][r0] = wv0.w;
        Ws[c0 + 0][r1] = wv1.x; Ws[c0 + 1][r1] = wv1.y;
        Ws[c0 + 2][r1] = wv1.z; Ws[c0 + 3][r1] = wv1.w;
        __syncthreads();

#pragma unroll
        for (int kk = 0; kk < 16; kk++) {
            float a[8], b[8];
            *(float4*)&a[0] = *(const float4*)&As[kk][(ty << 3) + 0];
            *(float4*)&a[4] = *(const float4*)&As[kk][(ty << 3) + 4];
            *(float4*)&b[0] = *(const float4*)&Ws[kk][(tx << 3) + 0];
            *(float4*)&b[4] = *(const float4*)&Ws[kk][(tx << 3) + 4];
#pragma unroll
            for (int i = 0; i < 8; i++)
#pragma unroll
                for (int j = 0; j < 8; j++)
                    acc[i][j] = fmaf(a[i], b[j], acc[i][j]);
        }
        __syncthreads();
    }

    float bi[8];
#pragma unroll
    for (int j = 0; j < 8; j++) bi[j] = bias[n0 + (tx << 3) + j];

#pragma unroll
    for (int i = 0; i < 8; i++) {
        size_t row = (size_t)(m0 + (ty << 3) + i) * N + n0 + (tx << 3);
        float v[8];
#pragma unroll
        for (int j = 0; j < 8; j++) {
            float c = acc[i][j] + bi[j];
            if (DO_GELU) c = gelu_exact(c);
            v[j] = c;
        }
        *(float4*)&C[row + 0] = make_float4(v[0], v[1], v[2], v[3]);
        *(float4*)&C[row + 4] = make_float4(v[4], v[5], v[6], v[7]);
    }
}

// ---------------------------------------------------------------------------
// Local causal attention, window=5. One warp per (token, head). hd=64:
// each lane holds dims {lane, lane+32}.
// ---------------------------------------------------------------------------
__global__ __launch_bounds__(256)
void attn_kernel(const float* __restrict__ qkv, float* __restrict__ attn)
{
    const int w    = (blockIdx.x * blockDim.x + threadIdx.x) >> 5;
    const int lane = threadIdx.x & 31;
    if (w >= MTOK * HEADS) return;
    const int m = w / HEADS;
    const int h = w - m * HEADS;
    const int s = m & (SEQ - 1);

    const float* qp = qkv + (size_t)m * (3 * DIMX) + h * HD;
    const float qa = qp[lane];
    const float qb = qp[lane + 32];

    const int jlo = (s >= WIN - 1) ? (s - (WIN - 1)) : 0;
    const int cnt = s - jlo + 1;
    const int mlo = m - (s - jlo);

    float sc[WIN];
#pragma unroll
    for (int t = 0; t < WIN; t++) {
        sc[t] = -3.0e38f;
        if (t < cnt) {
            const float* kp = qkv + (size_t)(mlo + t) * (3 * DIMX) + DIMX + h * HD;
            float d = qa * kp[lane] + qb * kp[lane + 32];
#pragma unroll
            for (int o = 16; o > 0; o >>= 1) d += __shfl_xor_sync(0xffffffffu, d, o);
            sc[t] = d * 0.125f;   // 1/sqrt(64)
        }
    }
    float mx = sc[0];
#pragma unroll
    for (int t = 1; t < WIN; t++) mx = fmaxf(mx, sc[t]);
    float p[WIN], sum = 0.0f;
#pragma unroll
    for (int t = 0; t < WIN; t++) {
        p[t] = (t < cnt) ? __expf(sc[t] - mx) : 0.0f;
        sum += p[t];
    }
    const float inv = 1.0f / sum;

    float oa = 0.0f, ob = 0.0f;
#pragma unroll
    for (int t = 0; t < WIN; t++) {
        if (t < cnt) {
            const float* vp = qkv + (size_t)(mlo + t) * (3 * DIMX) + 2 * DIMX + h * HD;
            oa = fmaf(p[t], vp[lane], oa);
            ob = fmaf(p[t], vp[lane + 32], ob);
        }
    }
    attn[(size_t)m * DIMX + h * HD + lane]      = oa * inv;
    attn[(size_t)m * DIMX + h * HD + lane + 32] = ob * inv;
}

// ---------------------------------------------------------------------------
// Fused residual + LayerNorm: out = LN(A + B) * g + beta. One block per row.
// ---------------------------------------------------------------------------
__global__ __launch_bounds__(256)
void ln_residual_kernel(const float* __restrict__ A, const float* __restrict__ Bv,
                        const float* __restrict__ g, const float* __restrict__ beta,
                        float* __restrict__ out)
{
    const int m   = blockIdx.x;
    const int tid = threadIdx.x;
    const float* a = A  + (size_t)m * DIMX;
    const float* b = Bv + (size_t)m * DIMX;

    float v[4];
    float s = 0.0f, s2 = 0.0f;
#pragma unroll
    for (int i = 0; i < 4; i++) {
        int idx = tid + i * 256;
        v[i] = a[idx] + b[idx];
        s  += v[i];
        s2 += v[i] * v[i];
    }
#pragma unroll
    for (int o = 16; o > 0; o >>= 1) {
        s  += __shfl_xor_sync(0xffffffffu, s,  o);
        s2 += __shfl_xor_sync(0xffffffffu, s2, o);
    }
    __shared__ float shs[8], shs2[8];
    __shared__ float sh_mean, sh_rstd;
    const int wid = tid >> 5, lane = tid & 31;
    if (lane == 0) { shs[wid] = s; shs2[wid] = s2; }
    __syncthreads();
    if (tid == 0) {
        float S = 0.0f, S2 = 0.0f;
#pragma unroll
        for (int i = 0; i < 8; i++) { S += shs[i]; S2 += shs2[i]; }
        float mean = S * (1.0f / DIMX);
        float var  = S2 * (1.0f / DIMX) - mean * mean;
        sh_mean = mean;
        sh_rstd = rsqrtf(var + EPSLN);
    }
    __syncthreads();
    const float mean = sh_mean, rstd = sh_rstd;
#pragma unroll
    for (int i = 0; i < 4; i++) {
        int idx = tid + i * 256;
        out[(size_t)m * DIMX + idx] = (v[i] - mean) * rstd * g[idx] + beta[idx];
    }
}

// ---------------------------------------------------------------------------
// kernel_launch
// Inputs: x, w_in, b_in, w_out, b_out, ln1_g, ln1_b, ln2_g, ln2_b, w1, b1, w2, b2
// ---------------------------------------------------------------------------
extern "C" void kernel_launch(void* const* d_in, const int* in_sizes, int n_in,
                              void* d_out, int out_size)
{
    const float* x     = (const float*)d_in[0];
    const float* w_in  = (const float*)d_in[1];
    const float* b_in  = (const float*)d_in[2];
    const float* w_out = (const float*)d_in[3];
    const float* b_out = (const float*)d_in[4];
    const float* ln1_g = (const float*)d_in[5];
    const float* ln1_b = (const float*)d_in[6];
    const float* ln2_g = (const float*)d_in[7];
    const float* ln2_b = (const float*)d_in[8];
    const float* w1    = (const float*)d_in[9];
    const float* b1    = (const float*)d_in[10];
    const float* w2    = (const float*)d_in[11];
    const float* b2    = (const float*)d_in[12];
    float* out = (float*)d_out;

    float *qkv, *attn, *attnout, *x1, *hbuf, *mlp;
    cudaGetSymbolAddress((void**)&qkv,     g_qkv);
    cudaGetSymbolAddress((void**)&attn,    g_attn);
    cudaGetSymbolAddress((void**)&attnout, g_attnout);
    cudaGetSymbolAddress((void**)&x1,      g_x1);
    cudaGetSymbolAddress((void**)&hbuf,    g_h);
    cudaGetSymbolAddress((void**)&mlp,     g_mlp);

    // 1. qkv = x @ w_in^T + b_in        [4096, 3072]
    gemm_nt_kernel<0><<<dim3(3 * DIMX / 128, MTOK / 128), 256>>>(
        x, w_in, b_in, qkv, MTOK, 3 * DIMX, DIMX);

    // 2. windowed causal attention      [4096, 1024]
    attn_kernel<<<(MTOK * HEADS * 32) / 256, 256>>>(qkv, attn);

    // 3. attnout = attn @ w_out^T + b_out
    gemm_nt_kernel<0><<<dim3(DIMX / 128, MTOK / 128), 256>>>(
        attn, w_out, b_out, attnout, MTOK, DIMX, DIMX);

    // 4. x1 = LN1(x + attnout)
    ln_residual_kernel<<<MTOK, 256>>>(x, attnout, ln1_g, ln1_b, x1);

    // 5. h = gelu(x1 @ w1^T + b1)       [4096, 4096]
    gemm_nt_kernel<1><<<dim3(4 * DIMX / 128, MTOK / 128), 256>>>(
        x1, w1, b1, hbuf, MTOK, 4 * DIMX, DIMX);

    // 6. mlp = h @ w2^T + b2            [4096, 1024], K = 4096
    gemm_nt_kernel<0><<<dim3(DIMX / 128, MTOK / 128), 256>>>(
        hbuf, w2, b2, mlp, MTOK, DIMX, 4 * DIMX);

    // 7. out = LN2(x1 + mlp)
    ln_residual_kernel<<<MTOK, 256>>>(x1, mlp, ln2_g, ln2_b, out);

    (void)in_sizes; (void)n_in; (void)out_size;
}

// round 5
// speedup vs baseline: 1.0005x; 1.0005x over previous
#include <cuda_runtime.h>
#include <math.h>

// Problem constants
#define DIMX   1024
#define HEADS  16
#define HD     64
#define WIN    5
#define BATCH  2
#define SEQ    2048
#define MTOK   (BATCH * SEQ)      // 4096 tokens
#define EPSLN  1e-5f

// ---------------------------------------------------------------------------
// Scratch (device globals: no runtime allocation allowed)
// ---------------------------------------------------------------------------
__device__ float g_qkv    [MTOK * 3 * DIMX];   // 50 MB
__device__ float g_attn   [MTOK * DIMX];
__device__ float g_attnout[MTOK * DIMX];
__device__ float g_x1     [MTOK * DIMX];
__device__ float g_h      [MTOK * 4 * DIMX];   // 67 MB
__device__ float g_mlp    [MTOK * DIMX];

// ---------------------------------------------------------------------------
// GEMM (NT): C[m,n] = sum_k A[m*K+k] * W[n*K+k] + bias[n], optional exact GELU
// Tile: 128x128x16, 256 threads, 8x8 per-thread microtile.
// ---------------------------------------------------------------------------
__device__ __forceinline__ float gelu_exact(float x) {
    return 0.5f * x * (1.0f + erff(x * 0.70710678118654752440f));
}

template <int DO_GELU>
__global__ __launch_bounds__(256, 2)
void gemm_nt_kernel(const float* __restrict__ A, const float* __restrict__ W,
                    const float* __restrict__ bias, float* __restrict__ C,
                    int M, int N, int K)
{
    __shared__ float As[16][128];
    __shared__ float Ws[16][128];

    const int tid = threadIdx.x;
    const int tx  = tid & 15;          // N direction (16 threads)
    const int ty  = tid >> 4;          // M direction (16 threads)
    const int m0  = blockIdx.y << 7;
    const int n0  = blockIdx.x << 7;

    // Global-load mapping: 128x16 tile = 512 float4, 2 per thread
    const int r0 = tid >> 2;           // rows 0..63
    const int c0 = (tid & 3) << 2;     // col offset 0,4,8,12
    const int r1 = r0 + 64;            // rows 64..127

    float acc[8][8];
#pragma unroll
    for (int i = 0; i < 8; i++)
#pragma unroll
        for (int j = 0; j < 8; j++) acc[i][j] = 0.0f;

    const float* Ap = A + (size_t)m0 * K;
    const float* Wp = W + (size_t)n0 * K;

    for (int k0 = 0; k0 < K; k0 += 16) {
        float4 av0 = *(const float4*)(Ap + (size_t)r0 * K + k0 + c0);
        float4 av1 = *(const float4*)(Ap + (size_t)r1 * K + k0 + c0);
        float4 wv0 = *(const float4*)(Wp + (size_t)r0 * K + k0 + c0);
        float4 wv1 = *(const float4*)(Wp + (size_t)r1 * K + k0 + c0);

        As[c0 + 0][r0] = av0.x; As[c0 + 1][r0] = av0.y;
        As[c0 + 2][r0] = av0.z; As[c0 + 3][r0] = av0.w;
        As[c0 + 0][r1] = av1.x; As[c0 + 1][r1] = av1.y;
        As[c0 + 2][r1] = av1.z; As[c0 + 3][r1] = av1.w;
        Ws[c0 + 0][r0] = wv0.x; Ws[c0 + 1][r0] = wv0.y;
        Ws[c0 + 2][r0] = wv0.z; Ws[c0 + 3][r0] = wv0.w;
        Ws[c0 + 0][r1] = wv1.x; Ws[c0 + 1][r1] = wv1.y;
        Ws[c0 + 2][r1] = wv1.z; Ws[c0 + 3][r1] = wv1.w;
        __syncthreads();

#pragma unroll
        for (int kk = 0; kk < 16; kk++) {
            float a[8], b[8];
            *(float4*)&a[0] = *(const float4*)&As[kk][(ty << 3) + 0];
            *(float4*)&a[4] = *(const float4*)&As[kk][(ty << 3) + 4];
            *(float4*)&b[0] = *(const float4*)&Ws[kk][(tx << 3) + 0];
            *(float4*)&b[4] = *(const float4*)&Ws[kk][(tx << 3) + 4];
#pragma unroll
            for (int i = 0; i < 8; i++)
#pragma unroll
                for (int j = 0; j < 8; j++)
                    acc[i][j] = fmaf(a[i], b[j], acc[i][j]);
        }
        __syncthreads();
    }

    float bi[8];
#pragma unroll
    for (int j = 0; j < 8; j++) bi[j] = bias[n0 + (tx << 3) + j];

#pragma unroll
    for (int i = 0; i < 8; i++) {
        size_t row = (size_t)(m0 + (ty << 3) + i) * N + n0 + (tx << 3);
        float v[8];
#pragma unroll
        for (int j = 0; j < 8; j++) {
            float c = acc[i][j] + bi[j];
            if (DO_GELU) c = gelu_exact(c);
            v[j] = c;
        }
        *(float4*)&C[row + 0] = make_float4(v[0], v[1], v[2], v[3]);
        *(float4*)&C[row + 4] = make_float4(v[4], v[5], v[6], v[7]);
    }
}

// ---------------------------------------------------------------------------
// Local causal attention, window=5. One warp per (token, head). hd=64:
// each lane holds dims {lane, lane+32}.
// ---------------------------------------------------------------------------
__global__ __launch_bounds__(256)
void attn_kernel(const float* __restrict__ qkv, float* __restrict__ attn)
{
    const int w    = (blockIdx.x * blockDim.x + threadIdx.x) >> 5;
    const int lane = threadIdx.x & 31;
    if (w >= MTOK * HEADS) return;
    const int m = w / HEADS;
    const int h = w - m * HEADS;
    const int s = m & (SEQ - 1);

    const float* qp = qkv + (size_t)m * (3 * DIMX) + h * HD;
    const float qa = qp[lane];
    const float qb = qp[lane + 32];

    const int jlo = (s >= WIN - 1) ? (s - (WIN - 1)) : 0;
    const int cnt = s - jlo + 1;
    const int mlo = m - (s - jlo);

    float sc[WIN];
#pragma unroll
    for (int t = 0; t < WIN; t++) {
        sc[t] = -3.0e38f;
        if (t < cnt) {
            const float* kp = qkv + (size_t)(mlo + t) * (3 * DIMX) + DIMX + h * HD;
            float d = qa * kp[lane] + qb * kp[lane + 32];
#pragma unroll
            for (int o = 16; o > 0; o >>= 1) d += __shfl_xor_sync(0xffffffffu, d, o);
            sc[t] = d * 0.125f;   // 1/sqrt(64)
        }
    }
    float mx = sc[0];
#pragma unroll
    for (int t = 1; t < WIN; t++) mx = fmaxf(mx, sc[t]);
    float p[WIN], sum = 0.0f;
#pragma unroll
    for (int t = 0; t < WIN; t++) {
        p[t] = (t < cnt) ? __expf(sc[t] - mx) : 0.0f;
        sum += p[t];
    }
    const float inv = 1.0f / sum;

    float oa = 0.0f, ob = 0.0f;
#pragma unroll
    for (int t = 0; t < WIN; t++) {
        if (t < cnt) {
            const float* vp = qkv + (size_t)(mlo + t) * (3 * DIMX) + 2 * DIMX + h * HD;
            oa = fmaf(p[t], vp[lane], oa);
            ob = fmaf(p[t], vp[lane + 32], ob);
        }
    }
    attn[(size_t)m * DIMX + h * HD + lane]      = oa * inv;
    attn[(size_t)m * DIMX + h * HD + lane + 32] = ob * inv;
}

// ---------------------------------------------------------------------------
// Fused residual + LayerNorm: out = LN(A + B) * g + beta. One block per row.
// ---------------------------------------------------------------------------
__global__ __launch_bounds__(256)
void ln_residual_kernel(const float* __restrict__ A, const float* __restrict__ Bv,
                        const float* __restrict__ g, const float* __restrict__ beta,
                        float* __restrict__ out)
{
    const int m   = blockIdx.x;
    const int tid = threadIdx.x;
    const float* a = A  + (size_t)m * DIMX;
    const float* b = Bv + (size_t)m * DIMX;

    float v[4];
    float s = 0.0f, s2 = 0.0f;
#pragma unroll
    for (int i = 0; i < 4; i++) {
        int idx = tid + i * 256;
        v[i] = a[idx] + b[idx];
        s  += v[i];
        s2 += v[i] * v[i];
    }
#pragma unroll
    for (int o = 16; o > 0; o >>= 1) {
        s  += __shfl_xor_sync(0xffffffffu, s,  o);
        s2 += __shfl_xor_sync(0xffffffffu, s2, o);
    }
    __shared__ float shs[8], shs2[8];
    __shared__ float sh_mean, sh_rstd;
    const int wid = tid >> 5, lane = tid & 31;
    if (lane == 0) { shs[wid] = s; shs2[wid] = s2; }
    __syncthreads();
    if (tid == 0) {
        float S = 0.0f, S2 = 0.0f;
#pragma unroll
        for (int i = 0; i < 8; i++) { S += shs[i]; S2 += shs2[i]; }
        float mean = S * (1.0f / DIMX);
        float var  = S2 * (1.0f / DIMX) - mean * mean;
        sh_mean = mean;
        sh_rstd = rsqrtf(var + EPSLN);
    }
    __syncthreads();
    const float mean = sh_mean, rstd = sh_rstd;
#pragma unroll
    for (int i = 0; i < 4; i++) {
        int idx = tid + i * 256;
        out[(size_t)m * DIMX + idx] = (v[i] - mean) * rstd * g[idx] + beta[idx];
    }
}

// ---------------------------------------------------------------------------
// kernel_launch
// Inputs: x, w_in, b_in, w_out, b_out, ln1_g, ln1_b, ln2_g, ln2_b, w1, b1, w2, b2
// ---------------------------------------------------------------------------
extern "C" void kernel_launch(void* const* d_in, const int* in_sizes, int n_in,
                              void* d_out, int out_size)
{
    const float* x     = (const float*)d_in[0];
    const float* w_in  = (const float*)d_in[1];
    const float* b_in  = (const float*)d_in[2];
    const float* w_out = (const float*)d_in[3];
    const float* b_out = (const float*)d_in[4];
    const float* ln1_g = (const float*)d_in[5];
    const float* ln1_b = (const float*)d_in[6];
    const float* ln2_g = (const float*)d_in[7];
    const float* ln2_b = (const float*)d_in[8];
    const float* w1    = (const float*)d_in[9];
    const float* b1    = (const float*)d_in[10];
    const float* w2    = (const float*)d_in[11];
    const float* b2    = (const float*)d_in[12];
    float* out = (float*)d_out;

    float *qkv, *attn, *attnout, *x1, *hbuf, *mlp;
    cudaGetSymbolAddress((void**)&qkv,     g_qkv);
    cudaGetSymbolAddress((void**)&attn,    g_attn);
    cudaGetSymbolAddress((void**)&attnout, g_attnout);
    cudaGetSymbolAddress((void**)&x1,      g_x1);
    cudaGetSymbolAddress((void**)&hbuf,    g_h);
    cudaGetSymbolAddress((void**)&mlp,     g_mlp);

    // 1. qkv = x @ w_in^T + b_in        [4096, 3072]
    gemm_nt_kernel<0><<<dim3(3 * DIMX / 128, MTOK / 128), 256>>>(
        x, w_in, b_in, qkv, MTOK, 3 * DIMX, DIMX);

    // 2. windowed causal attention      [4096, 1024]
    attn_kernel<<<(MTOK * HEADS * 32) / 256, 256>>>(qkv, attn);

    // 3. attnout = attn @ w_out^T + b_out
    gemm_nt_kernel<0><<<dim3(DIMX / 128, MTOK / 128), 256>>>(
        attn, w_out, b_out, attnout, MTOK, DIMX, DIMX);

    // 4. x1 = LN1(x + attnout)
    ln_residual_kernel<<<MTOK, 256>>>(x, attnout, ln1_g, ln1_b, x1);

    // 5. h = gelu(x1 @ w1^T + b1)       [4096, 4096]
    gemm_nt_kernel<1><<<dim3(4 * DIMX / 128, MTOK / 128), 256>>>(
        x1, w1, b1, hbuf, MTOK, 4 * DIMX, DIMX);

    // 6. mlp = h @ w2^T + b2            [4096, 1024], K = 4096
    gemm_nt_kernel<0><<<dim3(DIMX / 128, MTOK / 128), 256>>>(
        hbuf, w2, b2, mlp, MTOK, DIMX, 4 * DIMX);

    // 7. out = LN2(x1 + mlp)
    ln_residual_kernel<<<MTOK, 256>>>(x1, mlp, ln2_g, ln2_b, out);

    (void)in_sizes; (void)n_in; (void)out_size;
}

// round 7
// speedup vs baseline: 2.8964x; 2.8948x over previous
#include <cuda_runtime.h>
#include <cuda_bf16.h>
#include <math.h>
#include <stdint.h>

#define DIMX   1024
#define HEADS  16
#define HD     64
#define WIN    5
#define SEQ    2048
#define MTOK   4096
#define EPSLN  1e-5f

// ===========================================================================
// PTX helpers (baseline compute_103-safe: cp.async / ldmatrix / mma.sync)
// ===========================================================================
__device__ __forceinline__ uint32_t smem_to_u32(const void* p) {
    uint32_t a;
    asm("{ .reg .u64 t; cvta.to.shared.u64 t, %1; cvt.u32.u64 %0, t; }" : "=r"(a) : "l"(p));
    return a;
}
__device__ __forceinline__ void cp16(uint32_t dst, const void* src) {
    asm volatile("cp.async.cg.shared.global [%0], [%1], 16;" :: "r"(dst), "l"(src) : "memory");
}
#define CP_COMMIT() asm volatile("cp.async.commit_group;" ::: "memory")
#define CP_WAIT0()  asm volatile("cp.async.wait_group 0;"  ::: "memory")

__device__ __forceinline__ void ldsm4(uint32_t* r, uint32_t addr) {
    asm volatile("ldmatrix.sync.aligned.m8n8.x4.shared.b16 {%0,%1,%2,%3}, [%4];"
        : "=r"(r[0]), "=r"(r[1]), "=r"(r[2]), "=r"(r[3]) : "r"(addr));
}
__device__ __forceinline__ void ldsm2(uint32_t* r, uint32_t addr) {
    asm volatile("ldmatrix.sync.aligned.m8n8.x2.shared.b16 {%0,%1}, [%2];"
        : "=r"(r[0]), "=r"(r[1]) : "r"(addr));
}
__device__ __forceinline__ void mma16816(float* d, const uint32_t* a, const uint32_t* b) {
    asm volatile("mma.sync.aligned.m16n8k16.row.col.f32.bf16.bf16.f32 "
        "{%0,%1,%2,%3}, {%4,%5,%6,%7}, {%8,%9}, {%0,%1,%2,%3};"
        : "+f"(d[0]), "+f"(d[1]), "+f"(d[2]), "+f"(d[3])
        : "r"(a[0]), "r"(a[1]), "r"(a[2]), "r"(a[3]), "r"(b[0]), "r"(b[1]));
}

// ===========================================================================
// Scratch (device globals)
// ===========================================================================
__device__ __align__(256) float g_qkv    [MTOK * 3 * DIMX];
__device__ __align__(256) float g_attnout[MTOK * DIMX];
__device__ __align__(256) float g_x1     [MTOK * DIMX];
__device__ __align__(256) float g_mlp    [MTOK * DIMX];

__device__ __align__(256) __nv_bfloat16 g_xs   [MTOK * 3 * DIMX];
__device__ __align__(256) __nv_bfloat16 g_attns[MTOK * 3 * DIMX];
__device__ __align__(256) __nv_bfloat16 g_x1s  [MTOK * 3 * DIMX];
__device__ __align__(256) __nv_bfloat16 g_hs   [MTOK * 12288];
__device__ __align__(256) __nv_bfloat16 g_wins [3072 * 3072];
__device__ __align__(256) __nv_bfloat16 g_wouts[1024 * 3072];
__device__ __align__(256) __nv_bfloat16 g_w1s  [4096 * 3072];
__device__ __align__(256) __nv_bfloat16 g_w2s  [1024 * 12288];

__device__ __forceinline__ void bsplit(float v, __nv_bfloat16& hi, __nv_bfloat16& lo) {
    hi = __float2bfloat16(v);
    lo = __float2bfloat16(v - __bfloat162float(hi));
}
__device__ __forceinline__ float gelu_exact(float x) {
    return 0.5f * x * (1.0f + erff(x * 0.70710678118654752440f));
}

// ===========================================================================
// fp32 -> bf16x3 split. WMODE 0: [hi|lo|hi] (acts). WMODE 1: [hi|hi|lo] (wts)
// ===========================================================================
template <int WMODE>
__global__ __launch_bounds__(256)
void conv_split_kernel(const float* __restrict__ in, __nv_bfloat16* __restrict__ out, int K)
{
    int idx = (blockIdx.x * 256 + threadIdx.x) * 4;
    int r = idx / K, k = idx - r * K;
    float4 v = *(const float4*)(in + (size_t)r * K + k);
    __nv_bfloat16 h0,l0,h1,l1,h2,l2,h3,l3;
    bsplit(v.x,h0,l0); bsplit(v.y,h1,l1); bsplit(v.z,h2,l2); bsplit(v.w,h3,l3);
    __nv_bfloat162 hA{h0,h1}, hB{h2,h3}, lA{l0,l1}, lB{l2,l3};
    size_t b = (size_t)r * 3 * K + k;
    *(__nv_bfloat162*)(out + b)     = hA;
    *(__nv_bfloat162*)(out + b + 2) = hB;
    if (WMODE == 0) {
        *(__nv_bfloat162*)(out + b + K)         = lA;
        *(__nv_bfloat162*)(out + b + K + 2)     = lB;
        *(__nv_bfloat162*)(out + b + 2 * K)     = hA;
        *(__nv_bfloat162*)(out + b + 2 * K + 2) = hB;
    } else {
        *(__nv_bfloat162*)(out + b + K)         = hA;
        *(__nv_bfloat162*)(out + b + K + 2)     = hB;
        *(__nv_bfloat162*)(out + b + 2 * K)     = lA;
        *(__nv_bfloat162*)(out + b + 2 * K + 2) = lB;
    }
}

// ===========================================================================
// HMMA GEMM: C[M,N] = A[M,K3] x W[N,K3]^T (+bias).
// Tile 128x128, 256 threads (8 warps, 2x4), warp tile 64x32.
// K-chunk 64 bf16 (128B swizzled rows), 2-stage cp.async pipeline.
// OUT_MODE 0: fp32 C + bias.  OUT_MODE 1: gelu(C+bias) split [hi|lo|hi].
// smem: stage s: A at s*32768, B at s*32768 + 16384. Total 65536 B.
// ===========================================================================
__device__ __forceinline__ void load_tiles_h(const __nv_bfloat16* A, const __nv_bfloat16* W,
                                             int K3, uint32_t sb, int tid,
                                             int m0, int n0, int c, int s)
{
    const __nv_bfloat16* Ab = A + (size_t)m0 * K3 + c * 64;
    const __nv_bfloat16* Wb = W + (size_t)n0 * K3 + c * 64;
    const uint32_t ab = sb + s * 32768;
    const uint32_t bb = ab + 16384;
#pragma unroll
    for (int i = 0; i < 4; i++) {            // A: 128 rows x 128B = 1024 chunks
        int id = tid + i * 256;
        int r = id >> 3, cb = (id & 7) * 16;
        uint32_t off = (uint32_t)(r * 128 + cb); off ^= (off >> 3) & 0x70;
        cp16(ab + off, (const char*)(Ab + (size_t)r * K3) + cb);
    }
#pragma unroll
    for (int i = 0; i < 4; i++) {            // B: 128 rows x 128B
        int id = tid + i * 256;
        int r = id >> 3, cb = (id & 7) * 16;
        uint32_t off = (uint32_t)(r * 128 + cb); off ^= (off >> 3) & 0x70;
        cp16(bb + off, (const char*)(Wb + (size_t)r * K3) + cb);
    }
    CP_COMMIT();
}

template <int OUT_MODE>
__global__ __launch_bounds__(256)
void gemm3_kernel(const __nv_bfloat16* __restrict__ A, const __nv_bfloat16* __restrict__ W,
                  const float* __restrict__ bias, float* __restrict__ outF,
                  __nv_bfloat16* __restrict__ outS, int Ntot, int K3)
{
    extern __shared__ char smem[];
    const uint32_t sb = smem_to_u32(smem);
    const int tid = threadIdx.x, wid = tid >> 5, lane = tid & 31;
    const int wm = wid >> 2, wn = wid & 3;          // 2 x 4 warps
    const int m0 = blockIdx.y * 128, n0 = blockIdx.x * 128;
    const int NC = K3 / 64;

    float acc[4][4][4];                              // [ma][na][frag]
#pragma unroll
    for (int i = 0; i < 4; i++)
#pragma unroll
        for (int j = 0; j < 4; j++)
#pragma unroll
            for (int q = 0; q < 4; q++) acc[i][j][q] = 0.0f;

    // ldmatrix per-lane row indices
    const int aq  = lane >> 3;                       // 0..3
    const int ari = lane & 7;
    const int arow = wm * 64 + (aq & 1) * 8 + ari;   // + ma*16
    const int akc  = (aq >> 1);                      // k chunk-of-8 offset (0/1)
    const int bq  = (lane >> 3) & 1;
    const int bri = lane & 7;
    const int brow = wn * 32 + bri;                  // + na*8
    const int bkc  = bq;

    load_tiles_h(A, W, K3, sb, tid, m0, n0, 0, 0);
    CP_WAIT0();
    __syncthreads();

    for (int c = 0; c < NC; c++) {
        const int s = c & 1;
        if (c + 1 < NC) load_tiles_h(A, W, K3, sb, tid, m0, n0, c + 1, s ^ 1);

        const uint32_t ab = sb + s * 32768;
        const uint32_t bb = ab + 16384;
#pragma unroll
        for (int ks = 0; ks < 4; ks++) {
            const int kc = ks * 2;                   // chunk-of-8 base (0,2,4,6)
            uint32_t afr[4][4], bfr[4][2];
#pragma unroll
            for (int ma = 0; ma < 4; ma++) {
                int r = arow + ma * 16;
                uint32_t addr = ab + r * 128 + (((kc + akc) ^ (ari)) << 4);
                ldsm4(afr[ma], addr);
            }
#pragma unroll
            for (int na = 0; na < 4; na++) {
                int r = brow + na * 8;
                uint32_t addr = bb + r * 128 + (((kc + bkc) ^ (bri)) << 4);
                ldsm2(bfr[na], addr);
            }
#pragma unroll
            for (int ma = 0; ma < 4; ma++)
#pragma unroll
                for (int na = 0; na < 4; na++)
                    mma16816(acc[ma][na], afr[ma], bfr[na]);
        }
        CP_WAIT0();
        __syncthreads();
    }

    // epilogue
    const int lrow = lane >> 2;                      // 0..7
    const int lcol = (lane & 3) * 2;
#pragma unroll
    for (int ma = 0; ma < 4; ma++) {
        const int r0 = m0 + wm * 64 + ma * 16 + lrow;
#pragma unroll
        for (int na = 0; na < 4; na++) {
            const int c0 = n0 + wn * 32 + na * 8 + lcol;
            float v0 = acc[ma][na][0] + bias[c0];
            float v1 = acc[ma][na][1] + bias[c0 + 1];
            float v2 = acc[ma][na][2] + bias[c0];
            float v3 = acc[ma][na][3] + bias[c0 + 1];
            if (OUT_MODE == 0) {
                *(float2*)(outF + (size_t)r0 * Ntot + c0)       = make_float2(v0, v1);
                *(float2*)(outF + (size_t)(r0+8) * Ntot + c0)   = make_float2(v2, v3);
            } else {
                v0 = gelu_exact(v0); v1 = gelu_exact(v1);
                v2 = gelu_exact(v2); v3 = gelu_exact(v3);
                __nv_bfloat16 h0,l0,h1,l1,h2,l2,h3,l3;
                bsplit(v0,h0,l0); bsplit(v1,h1,l1);
                bsplit(v2,h2,l2); bsplit(v3,h3,l3);
                {
                    size_t base = (size_t)r0 * 3 * Ntot + c0;
                    __nv_bfloat162 hp{h0,h1}, lp{l0,l1};
                    *(__nv_bfloat162*)(outS + base)            = hp;
                    *(__nv_bfloat162*)(outS + base + Ntot)     = lp;
                    *(__nv_bfloat162*)(outS + base + 2*Ntot)   = hp;
                }
                {
                    size_t base = (size_t)(r0+8) * 3 * Ntot + c0;
                    __nv_bfloat162 hp{h2,h3}, lp{l2,l3};
                    *(__nv_bfloat162*)(outS + base)            = hp;
                    *(__nv_bfloat162*)(outS + base + Ntot)     = lp;
                    *(__nv_bfloat162*)(outS + base + 2*Ntot)   = hp;
                }
            }
        }
    }
}

// ===========================================================================
// Local causal attention (fp32 in, bf16x3 split out)
// ===========================================================================
__global__ __launch_bounds__(256)
void attn_kernel(const float* __restrict__ qkv, __nv_bfloat16* __restrict__ attns)
{
    const int w    = (blockIdx.x * blockDim.x + threadIdx.x) >> 5;
    const int lane = threadIdx.x & 31;
    if (w >= MTOK * HEADS) return;
    const int m = w / HEADS, h = w - m * HEADS, s = m & (SEQ - 1);

    const float* qp = qkv + (size_t)m * (3 * DIMX) + h * HD;
    const float qa = qp[lane], qb = qp[lane + 32];
    const int jlo = (s >= WIN - 1) ? (s - (WIN - 1)) : 0;
    const int cnt = s - jlo + 1;
    const int mlo = m - (s - jlo);

    float sc[WIN];
#pragma unroll
    for (int t = 0; t < WIN; t++) {
        sc[t] = -3.0e38f;
        if (t < cnt) {
            const float* kp = qkv + (size_t)(mlo + t) * (3 * DIMX) + DIMX + h * HD;
            float d = qa * kp[lane] + qb * kp[lane + 32];
#pragma unroll
            for (int o = 16; o > 0; o >>= 1) d += __shfl_xor_sync(0xffffffffu, d, o);
            sc[t] = d * 0.125f;
        }
    }
    float mx = sc[0];
#pragma unroll
    for (int t = 1; t < WIN; t++) mx = fmaxf(mx, sc[t]);
    float p[WIN], sum = 0.0f;
#pragma unroll
    for (int t = 0; t < WIN; t++) { p[t] = (t < cnt) ? __expf(sc[t] - mx) : 0.0f; sum += p[t]; }
    const float inv = 1.0f / sum;

    float oa = 0.0f, ob = 0.0f;
#pragma unroll
    for (int t = 0; t < WIN; t++) {
        if (t < cnt) {
            const float* vp = qkv + (size_t)(mlo + t) * (3 * DIMX) + 2 * DIMX + h * HD;
            oa = fmaf(p[t], vp[lane], oa);
            ob = fmaf(p[t], vp[lane + 32], ob);
        }
    }
    const size_t base = (size_t)m * 3 * DIMX + h * HD;
    __nv_bfloat16 hi, lo;
    bsplit(oa * inv, hi, lo);
    attns[base + lane] = hi; attns[base + DIMX + lane] = lo; attns[base + 2*DIMX + lane] = hi;
    bsplit(ob * inv, hi, lo);
    attns[base + lane + 32] = hi; attns[base + DIMX + lane + 32] = lo; attns[base + 2*DIMX + lane + 32] = hi;
}

// ===========================================================================
// Residual + LayerNorm (optionally also emit bf16x3 split)
// ===========================================================================
template <int SPLIT>
__global__ __launch_bounds__(256)
void ln_residual_kernel(const float* __restrict__ A, const float* __restrict__ Bv,
                        const float* __restrict__ g, const float* __restrict__ beta,
                        float* __restrict__ out, __nv_bfloat16* __restrict__ outs)
{
    const int m = blockIdx.x, tid = threadIdx.x;
    const float* a = A  + (size_t)m * DIMX;
    const float* b = Bv + (size_t)m * DIMX;
    float v[4], s = 0.0f, s2 = 0.0f;
#pragma unroll
    for (int i = 0; i < 4; i++) {
        int idx = tid + i * 256;
        v[i] = a[idx] + b[idx];
        s += v[i]; s2 += v[i] * v[i];
    }
#pragma unroll
    for (int o = 16; o > 0; o >>= 1) {
        s  += __shfl_xor_sync(0xffffffffu, s,  o);
        s2 += __shfl_xor_sync(0xffffffffu, s2, o);
    }
    __shared__ float shs[8], shs2[8], shm, shr;
    const int wid = tid >> 5, lane = tid & 31;
    if (lane == 0) { shs[wid] = s; shs2[wid] = s2; }
    __syncthreads();
    if (tid == 0) {
        float S = 0.0f, S2 = 0.0f;
#pragma unroll
        for (int i = 0; i < 8; i++) { S += shs[i]; S2 += shs2[i]; }
        float mean = S * (1.0f / DIMX);
        shm = mean;
        shr = rsqrtf(S2 * (1.0f / DIMX) - mean * mean + EPSLN);
    }
    __syncthreads();
    const float mean = shm, rstd = shr;
#pragma unroll
    for (int i = 0; i < 4; i++) {
        int idx = tid + i * 256;
        float y = (v[i] - mean) * rstd * g[idx] + beta[idx];
        out[(size_t)m * DIMX + idx] = y;
        if (SPLIT) {
            __nv_bfloat16 hi, lo;
            bsplit(y, hi, lo);
            size_t base = (size_t)m * 3 * DIMX;
            outs[base + idx] = hi;
            outs[base + DIMX + idx] = lo;
            outs[base + 2 * DIMX + idx] = hi;
        }
    }
}

// ===========================================================================
// kernel_launch
// ===========================================================================
#define GEMM_SMEM 65536

extern "C" void kernel_launch(void* const* d_in, const int* in_sizes, int n_in,
                              void* d_out, int out_size)
{
    const float* x     = (const float*)d_in[0];
    const float* w_in  = (const float*)d_in[1];
    const float* b_in  = (const float*)d_in[2];
    const float* w_out = (const float*)d_in[3];
    const float* b_out = (const float*)d_in[4];
    const float* ln1_g = (const float*)d_in[5];
    const float* ln1_b = (const float*)d_in[6];
    const float* ln2_g = (const float*)d_in[7];
    const float* ln2_b = (const float*)d_in[8];
    const float* w1    = (const float*)d_in[9];
    const float* b1    = (const float*)d_in[10];
    const float* w2    = (const float*)d_in[11];
    const float* b2    = (const float*)d_in[12];
    float* out = (float*)d_out;

    float *qkv, *attnout, *x1, *mlp;
    __nv_bfloat16 *xs, *attns, *x1s, *hs, *wins, *wouts, *w1s, *w2s;
    cudaGetSymbolAddress((void**)&qkv,     g_qkv);
    cudaGetSymbolAddress((void**)&attnout, g_attnout);
    cudaGetSymbolAddress((void**)&x1,      g_x1);
    cudaGetSymbolAddress((void**)&mlp,     g_mlp);
    cudaGetSymbolAddress((void**)&xs,      g_xs);
    cudaGetSymbolAddress((void**)&attns,   g_attns);
    cudaGetSymbolAddress((void**)&x1s,     g_x1s);
    cudaGetSymbolAddress((void**)&hs,      g_hs);
    cudaGetSymbolAddress((void**)&wins,    g_wins);
    cudaGetSymbolAddress((void**)&wouts,   g_wouts);
    cudaGetSymbolAddress((void**)&w1s,     g_w1s);
    cudaGetSymbolAddress((void**)&w2s,     g_w2s);

    cudaFuncSetAttribute(gemm3_kernel<0>, cudaFuncAttributeMaxDynamicSharedMemorySize, GEMM_SMEM);
    cudaFuncSetAttribute(gemm3_kernel<1>, cudaFuncAttributeMaxDynamicSharedMemorySize, GEMM_SMEM);

    // splits
    conv_split_kernel<0><<<MTOK * DIMX / 1024, 256>>>(x, xs, DIMX);
    conv_split_kernel<1><<<3072 * 1024 / 1024, 256>>>(w_in,  wins,  1024);
    conv_split_kernel<1><<<1024 * 1024 / 1024, 256>>>(w_out, wouts, 1024);
    conv_split_kernel<1><<<4096 * 1024 / 1024, 256>>>(w1,    w1s,   1024);
    conv_split_kernel<1><<<1024 * 4096 / 1024, 256>>>(w2,    w2s,   4096);

    // 1. qkv = x @ w_in^T + b_in           [4096, 3072], K3=3072
    gemm3_kernel<0><<<dim3(24, 32), 256, GEMM_SMEM>>>(xs, wins, b_in, qkv, nullptr, 3072, 3072);
    // 2. attention -> split
    attn_kernel<<<(MTOK * HEADS * 32) / 256, 256>>>(qkv, attns);
    // 3. attnout = attn @ w_out^T + b_out  [4096, 1024], K3=3072
    gemm3_kernel<0><<<dim3(8, 32), 256, GEMM_SMEM>>>(attns, wouts, b_out, attnout, nullptr, 1024, 3072);
    // 4. x1 = LN1(x + attnout), + split
    ln_residual_kernel<1><<<MTOK, 256>>>(x, attnout, ln1_g, ln1_b, x1, x1s);
    // 5. h = gelu(x1 @ w1^T + b1) -> split [4096, 4096], K3=3072
    gemm3_kernel<1><<<dim3(32, 32), 256, GEMM_SMEM>>>(x1s, w1s, b1, nullptr, hs, 4096, 3072);
    // 6. mlp = h @ w2^T + b2               [4096, 1024], K3=12288
    gemm3_kernel<0><<<dim3(8, 32), 256, GEMM_SMEM>>>(hs, w2s, b2, mlp, nullptr, 1024, 12288);
    // 7. out = LN2(x1 + mlp)
    ln_residual_kernel<0><<<MTOK, 256>>>(x1, mlp, ln2_g, ln2_b, out, nullptr);

    (void)in_sizes; (void)n_in; (void)out_size;
}

// round 8
// speedup vs baseline: 3.0169x; 1.0416x over previous
#include <cuda_runtime.h>
#include <cuda_bf16.h>
#include <math.h>
#include <stdint.h>

#define DIMX   1024
#define HEADS  16
#define HD     64
#define WIN    5
#define SEQ    2048
#define MTOK   4096
#define EPSLN  1e-5f

// ===========================================================================
// PTX helpers (baseline compute_103-safe: cp.async / ldmatrix / mma.sync)
// ===========================================================================
__device__ __forceinline__ uint32_t smem_to_u32(const void* p) {
    uint32_t a;
    asm("{ .reg .u64 t; cvta.to.shared.u64 t, %1; cvt.u32.u64 %0, t; }" : "=r"(a) : "l"(p));
    return a;
}
__device__ __forceinline__ void cp16(uint32_t dst, const void* src) {
    asm volatile("cp.async.cg.shared.global [%0], [%1], 16;" :: "r"(dst), "l"(src) : "memory");
}
#define CP_COMMIT() asm volatile("cp.async.commit_group;" ::: "memory")
#define CP_WAIT0()  asm volatile("cp.async.wait_group 0;"  ::: "memory")

__device__ __forceinline__ void ldsm4(uint32_t* r, uint32_t addr) {
    asm volatile("ldmatrix.sync.aligned.m8n8.x4.shared.b16 {%0,%1,%2,%3}, [%4];"
        : "=r"(r[0]), "=r"(r[1]), "=r"(r[2]), "=r"(r[3]) : "r"(addr));
}
__device__ __forceinline__ void ldsm2(uint32_t* r, uint32_t addr) {
    asm volatile("ldmatrix.sync.aligned.m8n8.x2.shared.b16 {%0,%1}, [%2];"
        : "=r"(r[0]), "=r"(r[1]) : "r"(addr));
}
__device__ __forceinline__ void mma16816(float* d, const uint32_t* a, const uint32_t* b) {
    asm volatile("mma.sync.aligned.m16n8k16.row.col.f32.bf16.bf16.f32 "
        "{%0,%1,%2,%3}, {%4,%5,%6,%7}, {%8,%9}, {%0,%1,%2,%3};"
        : "+f"(d[0]), "+f"(d[1]), "+f"(d[2]), "+f"(d[3])
        : "r"(a[0]), "r"(a[1]), "r"(a[2]), "r"(a[3]), "r"(b[0]), "r"(b[1]));
}

// ===========================================================================
// Scratch (device globals).  Split layout: row stride 2K, [hi(K) | lo(K)].
// ===========================================================================
__device__ __align__(256) float g_qkv    [MTOK * 3 * DIMX];
__device__ __align__(256) float g_attnout[MTOK * DIMX];
__device__ __align__(256) float g_x1     [MTOK * DIMX];
__device__ __align__(256) float g_mlp    [MTOK * DIMX];

__device__ __align__(256) __nv_bfloat16 g_xs   [MTOK * 2 * DIMX];
__device__ __align__(256) __nv_bfloat16 g_attns[MTOK * 2 * DIMX];
__device__ __align__(256) __nv_bfloat16 g_x1s  [MTOK * 2 * DIMX];
__device__ __align__(256) __nv_bfloat16 g_hs   [MTOK * 8192];
__device__ __align__(256) __nv_bfloat16 g_wins [3072 * 2048];
__device__ __align__(256) __nv_bfloat16 g_wouts[1024 * 2048];
__device__ __align__(256) __nv_bfloat16 g_w1s  [4096 * 2048];
__device__ __align__(256) __nv_bfloat16 g_w2s  [1024 * 8192];

__device__ __forceinline__ void bsplit(float v, __nv_bfloat16& hi, __nv_bfloat16& lo) {
    hi = __float2bfloat16(v);
    lo = __float2bfloat16(v - __bfloat162float(hi));
}
__device__ __forceinline__ float gelu_exact(float x) {
    return 0.5f * x * (1.0f + erff(x * 0.70710678118654752440f));
}

// ===========================================================================
// fp32 -> bf16 [hi|lo] split (row stride 2K)
// ===========================================================================
__global__ __launch_bounds__(256)
void conv_split_kernel(const float* __restrict__ in, __nv_bfloat16* __restrict__ out, int K)
{
    int idx = (blockIdx.x * 256 + threadIdx.x) * 4;
    int r = idx / K, k = idx - r * K;
    float4 v = *(const float4*)(in + (size_t)r * K + k);
    __nv_bfloat16 h0,l0,h1,l1,h2,l2,h3,l3;
    bsplit(v.x,h0,l0); bsplit(v.y,h1,l1); bsplit(v.z,h2,l2); bsplit(v.w,h3,l3);
    __nv_bfloat162 hA{h0,h1}, hB{h2,h3}, lA{l0,l1}, lB{l2,l3};
    size_t b = (size_t)r * 2 * K + k;
    *(__nv_bfloat162*)(out + b)         = hA;
    *(__nv_bfloat162*)(out + b + 2)     = hB;
    *(__nv_bfloat162*)(out + b + K)     = lA;
    *(__nv_bfloat162*)(out + b + K + 2) = lB;
}

// ===========================================================================
// HMMA GEMM with fragment-level hi/lo compensation:
//   C = Ahi*Whi^T + Alo*Whi^T + Ahi*Wlo^T  (+bias)
// Tile 256x128, 512 threads (16 warps, 4x4), warp tile 64x32.
// K-chunk 64 (hi and lo planes), 2-stage cp.async pipeline.
// smem stage: Ahi 32K | Alo 32K | Whi 16K | Wlo 16K = 96K; 2 stages = 192K.
// OUT_MODE 0: fp32 C + bias.  OUT_MODE 1: gelu(C+bias) -> [hi|lo] split.
// ===========================================================================
#define STAGE_B 98304
#define GEMM_SMEM (2 * STAGE_B)

__device__ __forceinline__ void load_ab(const __nv_bfloat16* A, const __nv_bfloat16* W,
                                        int K, uint32_t sb, int tid,
                                        int m0, int n0, int c, int s)
{
    const size_t rb = (size_t)4 * K;                 // row bytes (2K bf16)
    const char* Ab = (const char*)A + (size_t)m0 * rb + (size_t)c * 128;
    const char* Wb = (const char*)W + (size_t)n0 * rb + (size_t)c * 128;
    const uint32_t lo_off = (uint32_t)(2 * K);       // lo plane byte offset in row
    const uint32_t ahi = sb + s * STAGE_B;
    const uint32_t alo = ahi + 32768;
    const uint32_t whi = ahi + 65536;
    const uint32_t wlo = ahi + 81920;
#pragma unroll
    for (int i = 0; i < 4; i++) {                    // A: 256 rows x 128B
        int id = tid + i * 512;
        int r = id >> 3, cb = (id & 7) * 16;
        uint32_t off = (uint32_t)(r * 128 + cb); off ^= (off >> 3) & 0x70;
        const char* src = Ab + (size_t)r * rb + cb;
        cp16(ahi + off, src);
        cp16(alo + off, src + lo_off);
    }
#pragma unroll
    for (int i = 0; i < 2; i++) {                    // W: 128 rows x 128B
        int id = tid + i * 512;
        int r = id >> 3, cb = (id & 7) * 16;
        uint32_t off = (uint32_t)(r * 128 + cb); off ^= (off >> 3) & 0x70;
        const char* src = Wb + (size_t)r * rb + cb;
        cp16(whi + off, src);
        cp16(wlo + off, src + lo_off);
    }
    CP_COMMIT();
}

template <int OUT_MODE>
__global__ __launch_bounds__(512, 1)
void gemm2_kernel(const __nv_bfloat16* __restrict__ A, const __nv_bfloat16* __restrict__ W,
                  const float* __restrict__ bias, float* __restrict__ outF,
                  __nv_bfloat16* __restrict__ outS, int Ntot, int K)
{
    extern __shared__ char smem[];
    const uint32_t sb = smem_to_u32(smem);
    const int tid = threadIdx.x, wid = tid >> 5, lane = tid & 31;
    const int wm = wid >> 2, wn = wid & 3;           // 4 x 4 warps
    const int m0 = blockIdx.y * 256, n0 = blockIdx.x * 128;
    const int NC = K / 64;

    float acc[4][4][4];
#pragma unroll
    for (int i = 0; i < 4; i++)
#pragma unroll
        for (int j = 0; j < 4; j++)
#pragma unroll
            for (int q = 0; q < 4; q++) acc[i][j][q] = 0.0f;

    const int aq  = lane >> 3;
    const int ari = lane & 7;
    const int arow = wm * 64 + (aq & 1) * 8 + ari;   // + ma*16
    const int akc  = aq >> 1;
    const int bq   = (lane >> 3) & 1;
    const int bri  = lane & 7;
    const int brow = wn * 32 + bri;                  // + na*8
    const int bkc  = bq;

    load_ab(A, W, K, sb, tid, m0, n0, 0, 0);
    CP_WAIT0();
    __syncthreads();

    for (int c = 0; c < NC; c++) {
        const int s = c & 1;
        if (c + 1 < NC) load_ab(A, W, K, sb, tid, m0, n0, c + 1, s ^ 1);

        const uint32_t ahi = sb + s * STAGE_B;
        const uint32_t alo = ahi + 32768;
        const uint32_t whi = ahi + 65536;
        const uint32_t wlo = ahi + 81920;
#pragma unroll
        for (int ks = 0; ks < 4; ks++) {
            const int kc = ks * 2;
            uint32_t bh[4][2], bl[4][2];
            const uint32_t bsw = ((uint32_t)((kc + bkc) ^ bri)) << 4;
#pragma unroll
            for (int na = 0; na < 4; na++) {
                const uint32_t rb2 = (brow + na * 8) * 128 + bsw;
                ldsm2(bh[na], whi + rb2);
                ldsm2(bl[na], wlo + rb2);
            }
            const uint32_t asw = ((uint32_t)((kc + akc) ^ ari)) << 4;
#pragma unroll
            for (int ma = 0; ma < 4; ma++) {
                const uint32_t ra = (arow + ma * 16) * 128 + asw;
                uint32_t ah[4], al[4];
                ldsm4(ah, ahi + ra);
                ldsm4(al, alo + ra);
#pragma unroll
                for (int na = 0; na < 4; na++) {
                    mma16816(acc[ma][na], ah, bh[na]);
                    mma16816(acc[ma][na], al, bh[na]);
                    mma16816(acc[ma][na], ah, bl[na]);
                }
            }
        }
        CP_WAIT0();
        __syncthreads();
    }

    // epilogue
    const int lrow = lane >> 2;
    const int lcol = (lane & 3) * 2;
#pragma unroll
    for (int ma = 0; ma < 4; ma++) {
        const int r0 = m0 + wm * 64 + ma * 16 + lrow;
#pragma unroll
        for (int na = 0; na < 4; na++) {
            const int c0 = n0 + wn * 32 + na * 8 + lcol;
            float v0 = acc[ma][na][0] + bias[c0];
            float v1 = acc[ma][na][1] + bias[c0 + 1];
            float v2 = acc[ma][na][2] + bias[c0];
            float v3 = acc[ma][na][3] + bias[c0 + 1];
            if (OUT_MODE == 0) {
                *(float2*)(outF + (size_t)r0 * Ntot + c0)     = make_float2(v0, v1);
                *(float2*)(outF + (size_t)(r0+8) * Ntot + c0) = make_float2(v2, v3);
            } else {
                v0 = gelu_exact(v0); v1 = gelu_exact(v1);
                v2 = gelu_exact(v2); v3 = gelu_exact(v3);
                __nv_bfloat16 h0,l0,h1,l1,h2,l2,h3,l3;
                bsplit(v0,h0,l0); bsplit(v1,h1,l1);
                bsplit(v2,h2,l2); bsplit(v3,h3,l3);
                {
                    size_t base = (size_t)r0 * 2 * Ntot + c0;
                    *(__nv_bfloat162*)(outS + base)        = __nv_bfloat162{h0,h1};
                    *(__nv_bfloat162*)(outS + base + Ntot) = __nv_bfloat162{l0,l1};
                }
                {
                    size_t base = (size_t)(r0+8) * 2 * Ntot + c0;
                    *(__nv_bfloat162*)(outS + base)        = __nv_bfloat162{h2,h3};
                    *(__nv_bfloat162*)(outS + base + Ntot) = __nv_bfloat162{l2,l3};
                }
            }
        }
    }
}

// ===========================================================================
// Local causal attention (fp32 in, [hi|lo] split out)
// ===========================================================================
__global__ __launch_bounds__(256)
void attn_kernel(const float* __restrict__ qkv, __nv_bfloat16* __restrict__ attns)
{
    const int w    = (blockIdx.x * blockDim.x + threadIdx.x) >> 5;
    const int lane = threadIdx.x & 31;
    if (w >= MTOK * HEADS) return;
    const int m = w / HEADS, h = w - m * HEADS, s = m & (SEQ - 1);

    const float* qp = qkv + (size_t)m * (3 * DIMX) + h * HD;
    const float qa = qp[lane], qb = qp[lane + 32];
    const int jlo = (s >= WIN - 1) ? (s - (WIN - 1)) : 0;
    const int cnt = s - jlo + 1;
    const int mlo = m - (s - jlo);

    float sc[WIN];
#pragma unroll
    for (int t = 0; t < WIN; t++) {
        sc[t] = -3.0e38f;
        if (t < cnt) {
            const float* kp = qkv + (size_t)(mlo + t) * (3 * DIMX) + DIMX + h * HD;
            float d = qa * kp[lane] + qb * kp[lane + 32];
#pragma unroll
            for (int o = 16; o > 0; o >>= 1) d += __shfl_xor_sync(0xffffffffu, d, o);
            sc[t] = d * 0.125f;
        }
    }
    float mx = sc[0];
#pragma unroll
    for (int t = 1; t < WIN; t++) mx = fmaxf(mx, sc[t]);
    float p[WIN], sum = 0.0f;
#pragma unroll
    for (int t = 0; t < WIN; t++) { p[t] = (t < cnt) ? __expf(sc[t] - mx) : 0.0f; sum += p[t]; }
    const float inv = 1.0f / sum;

    float oa = 0.0f, ob = 0.0f;
#pragma unroll
    for (int t = 0; t < WIN; t++) {
        if (t < cnt) {
            const float* vp = qkv + (size_t)(mlo + t) * (3 * DIMX) + 2 * DIMX + h * HD;
            oa = fmaf(p[t], vp[lane], oa);
            ob = fmaf(p[t], vp[lane + 32], ob);
        }
    }
    const size_t base = (size_t)m * 2 * DIMX + h * HD;
    __nv_bfloat16 hi, lo;
    bsplit(oa * inv, hi, lo);
    attns[base + lane] = hi; attns[base + DIMX + lane] = lo;
    bsplit(ob * inv, hi, lo);
    attns[base + lane + 32] = hi; attns[base + DIMX + lane + 32] = lo;
}

// ===========================================================================
// Residual + LayerNorm (optionally also emit [hi|lo] split)
// ===========================================================================
template <int SPLIT>
__global__ __launch_bounds__(256)
void ln_residual_kernel(const float* __restrict__ A, const float* __restrict__ Bv,
                        const float* __restrict__ g, const float* __restrict__ beta,
                        float* __restrict__ out, __nv_bfloat16* __restrict__ outs)
{
    const int m = blockIdx.x, tid = threadIdx.x;
    const float* a = A  + (size_t)m * DIMX;
    const float* b = Bv + (size_t)m * DIMX;
    float v[4], s = 0.0f, s2 = 0.0f;
#pragma unroll
    for (int i = 0; i < 4; i++) {
        int idx = tid + i * 256;
        v[i] = a[idx] + b[idx];
        s += v[i]; s2 += v[i] * v[i];
    }
#pragma unroll
    for (int o = 16; o > 0; o >>= 1) {
        s  += __shfl_xor_sync(0xffffffffu, s,  o);
        s2 += __shfl_xor_sync(0xffffffffu, s2, o);
    }
    __shared__ float shs[8], shs2[8], shm, shr;
    const int wid = tid >> 5, lane = tid & 31;
    if (lane == 0) { shs[wid] = s; shs2[wid] = s2; }
    __syncthreads();
    if (tid == 0) {
        float S = 0.0f, S2 = 0.0f;
#pragma unroll
        for (int i = 0; i < 8; i++) { S += shs[i]; S2 += shs2[i]; }
        float mean = S * (1.0f / DIMX);
        shm = mean;
        shr = rsqrtf(S2 * (1.0f / DIMX) - mean * mean + EPSLN);
    }
    __syncthreads();
    const float mean = shm, rstd = shr;
#pragma unroll
    for (int i = 0; i < 4; i++) {
        int idx = tid + i * 256;
        float y = (v[i] - mean) * rstd * g[idx] + beta[idx];
        out[(size_t)m * DIMX + idx] = y;
        if (SPLIT) {
            __nv_bfloat16 hi, lo;
            bsplit(y, hi, lo);
            size_t base = (size_t)m * 2 * DIMX;
            outs[base + idx] = hi;
            outs[base + DIMX + idx] = lo;
        }
    }
}

// ===========================================================================
// kernel_launch
// ===========================================================================
extern "C" void kernel_launch(void* const* d_in, const int* in_sizes, int n_in,
                              void* d_out, int out_size)
{
    const float* x     = (const float*)d_in[0];
    const float* w_in  = (const float*)d_in[1];
    const float* b_in  = (const float*)d_in[2];
    const float* w_out = (const float*)d_in[3];
    const float* b_out = (const float*)d_in[4];
    const float* ln1_g = (const float*)d_in[5];
    const float* ln1_b = (const float*)d_in[6];
    const float* ln2_g = (const float*)d_in[7];
    const float* ln2_b = (const float*)d_in[8];
    const float* w1    = (const float*)d_in[9];
    const float* b1    = (const float*)d_in[10];
    const float* w2    = (const float*)d_in[11];
    const float* b2    = (const float*)d_in[12];
    float* out = (float*)d_out;

    float *qkv, *attnout, *x1, *mlp;
    __nv_bfloat16 *xs, *attns, *x1s, *hs, *wins, *wouts, *w1s, *w2s;
    cudaGetSymbolAddress((void**)&qkv,     g_qkv);
    cudaGetSymbolAddress((void**)&attnout, g_attnout);
    cudaGetSymbolAddress((void**)&x1,      g_x1);
    cudaGetSymbolAddress((void**)&mlp,     g_mlp);
    cudaGetSymbolAddress((void**)&xs,      g_xs);
    cudaGetSymbolAddress((void**)&attns,   g_attns);
    cudaGetSymbolAddress((void**)&x1s,     g_x1s);
    cudaGetSymbolAddress((void**)&hs,      g_hs);
    cudaGetSymbolAddress((void**)&wins,    g_wins);
    cudaGetSymbolAddress((void**)&wouts,   g_wouts);
    cudaGetSymbolAddress((void**)&w1s,     g_w1s);
    cudaGetSymbolAddress((void**)&w2s,     g_w2s);

    cudaFuncSetAttribute(gemm2_kernel<0>, cudaFuncAttributeMaxDynamicSharedMemorySize, GEMM_SMEM);
    cudaFuncSetAttribute(gemm2_kernel<1>, cudaFuncAttributeMaxDynamicSharedMemorySize, GEMM_SMEM);

    // splits (all [hi|lo], row stride 2K)
    conv_split_kernel<<<MTOK * DIMX / 1024, 256>>>(x, xs, DIMX);
    conv_split_kernel<<<3072 * 1024 / 1024, 256>>>(w_in,  wins,  1024);
    conv_split_kernel<<<1024 * 1024 / 1024, 256>>>(w_out, wouts, 1024);
    conv_split_kernel<<<4096 * 1024 / 1024, 256>>>(w1,    w1s,   1024);
    conv_split_kernel<<<1024 * 4096 / 1024, 256>>>(w2,    w2s,   4096);

    // 1. qkv = x @ w_in^T + b_in           [4096, 3072], K=1024
    gemm2_kernel<0><<<dim3(24, 16), 512, GEMM_SMEM>>>(xs, wins, b_in, qkv, nullptr, 3072, 1024);
    // 2. attention -> split
    attn_kernel<<<(MTOK * HEADS * 32) / 256, 256>>>(qkv, attns);
    // 3. attnout = attn @ w_out^T + b_out  [4096, 1024], K=1024
    gemm2_kernel<0><<<dim3(8, 16), 512, GEMM_SMEM>>>(attns, wouts, b_out, attnout, nullptr, 1024, 1024);
    // 4. x1 = LN1(x + attnout), + split
    ln_residual_kernel<1><<<MTOK, 256>>>(x, attnout, ln1_g, ln1_b, x1, x1s);
    // 5. h = gelu(x1 @ w1^T + b1) -> split [4096, 4096], K=1024
    gemm2_kernel<1><<<dim3(32, 16), 512, GEMM_SMEM>>>(x1s, w1s, b1, nullptr, hs, 4096, 1024);
    // 6. mlp = h @ w2^T + b2               [4096, 1024], K=4096
    gemm2_kernel<0><<<dim3(8, 16), 512, GEMM_SMEM>>>(hs, w2s, b2, mlp, nullptr, 1024, 4096);
    // 7. out = LN2(x1 + mlp)
    ln_residual_kernel<0><<<MTOK, 256>>>(x1, mlp, ln2_g, ln2_b, out, nullptr);

    (void)in_sizes; (void)n_in; (void)out_size;
}

// round 9
// speedup vs baseline: 4.1491x; 1.3753x over previous
#include <cuda_runtime.h>
#include <cuda_fp16.h>
#include <math.h>
#include <stdint.h>

#define DIMX   1024
#define HEADS  16
#define HD     64
#define WIN    5
#define SEQ    2048
#define MTOK   4096
#define EPSLN  1e-5f

// ===========================================================================
// PTX helpers (baseline compute_103-safe: cp.async / ldmatrix / mma.sync)
// ===========================================================================
__device__ __forceinline__ uint32_t smem_to_u32(const void* p) {
    uint32_t a;
    asm("{ .reg .u64 t; cvta.to.shared.u64 t, %1; cvt.u32.u64 %0, t; }" : "=r"(a) : "l"(p));
    return a;
}
__device__ __forceinline__ void cp16(uint32_t dst, const void* src) {
    asm volatile("cp.async.cg.shared.global [%0], [%1], 16;" :: "r"(dst), "l"(src) : "memory");
}
#define CP_COMMIT() asm volatile("cp.async.commit_group;" ::: "memory")
#define CP_WAIT0()  asm volatile("cp.async.wait_group 0;"  ::: "memory")

__device__ __forceinline__ void ldsm4(uint32_t* r, uint32_t addr) {
    asm volatile("ldmatrix.sync.aligned.m8n8.x4.shared.b16 {%0,%1,%2,%3}, [%4];"
        : "=r"(r[0]), "=r"(r[1]), "=r"(r[2]), "=r"(r[3]) : "r"(addr));
}
__device__ __forceinline__ void ldsm2(uint32_t* r, uint32_t addr) {
    asm volatile("ldmatrix.sync.aligned.m8n8.x2.shared.b16 {%0,%1}, [%2];"
        : "=r"(r[0]), "=r"(r[1]) : "r"(addr));
}
__device__ __forceinline__ void mma16816(float* d, const uint32_t* a, const uint32_t* b) {
    asm volatile("mma.sync.aligned.m16n8k16.row.col.f32.f16.f16.f32 "
        "{%0,%1,%2,%3}, {%4,%5,%6,%7}, {%8,%9}, {%0,%1,%2,%3};"
        : "+f"(d[0]), "+f"(d[1]), "+f"(d[2]), "+f"(d[3])
        : "r"(a[0]), "r"(a[1]), "r"(a[2]), "r"(a[3]), "r"(b[0]), "r"(b[1]));
}

// ===========================================================================
// Scratch. Activations: [hi(K) | lo(K)] fp16, row stride 2K. Weights: plain fp16.
// ===========================================================================
__device__ __align__(256) float g_qkv    [MTOK * 3 * DIMX];
__device__ __align__(256) float g_attnout[MTOK * DIMX];
__device__ __align__(256) float g_x1     [MTOK * DIMX];
__device__ __align__(256) float g_mlp    [MTOK * DIMX];

__device__ __align__(256) __half g_xs   [MTOK * 2 * DIMX];
__device__ __align__(256) __half g_attns[MTOK * 2 * DIMX];
__device__ __align__(256) __half g_x1s  [MTOK * 2 * DIMX];
__device__ __align__(256) __half g_hs   [MTOK * 8192];
__device__ __align__(256) __half g_wins [3072 * 1024];
__device__ __align__(256) __half g_wouts[1024 * 1024];
__device__ __align__(256) __half g_w1s  [4096 * 1024];
__device__ __align__(256) __half g_w2s  [1024 * 4096];

__device__ __forceinline__ void hsplit(float v, __half& hi, __half& lo) {
    hi = __float2half_rn(v);
    lo = __float2half_rn(v - __half2float(hi));
}
__device__ __forceinline__ float gelu_exact(float x) {
    return 0.5f * x * (1.0f + erff(x * 0.70710678118654752440f));
}

// ===========================================================================
// fp32 -> fp16 [hi|lo] split (activations, row stride 2K)
// ===========================================================================
__global__ __launch_bounds__(256)
void conv_split_kernel(const float* __restrict__ in, __half* __restrict__ out, int K)
{
    int idx = (blockIdx.x * 256 + threadIdx.x) * 4;
    int r = idx / K, k = idx - r * K;
    float4 v = *(const float4*)(in + (size_t)r * K + k);
    __half h0,l0,h1,l1,h2,l2,h3,l3;
    hsplit(v.x,h0,l0); hsplit(v.y,h1,l1); hsplit(v.z,h2,l2); hsplit(v.w,h3,l3);
    size_t b = (size_t)r * 2 * K + k;
    *(__half2*)(out + b)         = __half2{h0,h1};
    *(__half2*)(out + b + 2)     = __half2{h2,h3};
    *(__half2*)(out + b + K)     = __half2{l0,l1};
    *(__half2*)(out + b + K + 2) = __half2{l2,l3};
}

// fp32 -> fp16 plain cast (weights)
__global__ __launch_bounds__(256)
void conv_cast_kernel(const float* __restrict__ in, __half* __restrict__ out)
{
    size_t idx = (size_t)(blockIdx.x * 256 + threadIdx.x) * 4;
    float4 v = *(const float4*)(in + idx);
    *(__half2*)(out + idx)     = __half2{__float2half_rn(v.x), __float2half_rn(v.y)};
    *(__half2*)(out + idx + 2) = __half2{__float2half_rn(v.z), __float2half_rn(v.w)};
}

// ===========================================================================
// HMMA GEMM, fp16 2-term compensation:
//   C = Ahi*W^T + Alo*W^T   (A split, W plain fp16)  (+bias)
// Tile 256x128, 512 threads (16 warps, 4x4), warp tile 64x32.
// K-chunk 64 (128B swizzled rows), 2-stage cp.async pipeline.
// smem stage: Ahi 32K | Alo 32K | W 16K = 80K; 2 stages = 160K.
// OUT_MODE 0: fp32 C + bias.  OUT_MODE 1: gelu(C+bias) -> [hi|lo] split.
// ===========================================================================
#define STAGE_B 81920
#define GEMM_SMEM (2 * STAGE_B)

__device__ __forceinline__ void load_ab(const __half* A, const __half* W,
                                        int K, uint32_t sb, int tid,
                                        int m0, int n0, int c, int s)
{
    const size_t arb = (size_t)4 * K;                // A row bytes (2K halves)
    const size_t wrb = (size_t)2 * K;                // W row bytes (K halves)
    const char* Ab = (const char*)A + (size_t)m0 * arb + (size_t)c * 128;
    const char* Wb = (const char*)W + (size_t)n0 * wrb + (size_t)c * 128;
    const uint32_t lo_off = (uint32_t)(2 * K);       // byte offset of lo plane
    const uint32_t ahi = sb + s * STAGE_B;
    const uint32_t alo = ahi + 32768;
    const uint32_t whi = ahi + 65536;
#pragma unroll
    for (int i = 0; i < 4; i++) {                    // A: 256 rows x 128B, hi+lo
        int id = tid + i * 512;
        int r = id >> 3, cb = (id & 7) * 16;
        uint32_t off = (uint32_t)(r * 128 + cb); off ^= (off >> 3) & 0x70;
        const char* src = Ab + (size_t)r * arb + cb;
        cp16(ahi + off, src);
        cp16(alo + off, src + lo_off);
    }
#pragma unroll
    for (int i = 0; i < 2; i++) {                    // W: 128 rows x 128B
        int id = tid + i * 512;
        int r = id >> 3, cb = (id & 7) * 16;
        uint32_t off = (uint32_t)(r * 128 + cb); off ^= (off >> 3) & 0x70;
        cp16(whi + off, Wb + (size_t)r * wrb + cb);
    }
    CP_COMMIT();
}

template <int OUT_MODE>
__global__ __launch_bounds__(512, 1)
void gemm2_kernel(const __half* __restrict__ A, const __half* __restrict__ W,
                  const float* __restrict__ bias, float* __restrict__ outF,
                  __half* __restrict__ outS, int Ntot, int K)
{
    extern __shared__ char smem[];
    const uint32_t sb = smem_to_u32(smem);
    const int tid = threadIdx.x, wid = tid >> 5, lane = tid & 31;
    const int wm = wid >> 2, wn = wid & 3;           // 4 x 4 warps
    const int m0 = blockIdx.y * 256, n0 = blockIdx.x * 128;
    const int NC = K / 64;

    float acc[4][4][4];
#pragma unroll
    for (int i = 0; i < 4; i++)
#pragma unroll
        for (int j = 0; j < 4; j++)
#pragma unroll
            for (int q = 0; q < 4; q++) acc[i][j][q] = 0.0f;

    const int aq  = lane >> 3;
    const int ari = lane & 7;
    const int arow = wm * 64 + (aq & 1) * 8 + ari;   // + ma*16
    const int akc  = aq >> 1;
    const int bq   = (lane >> 3) & 1;
    const int bri  = lane & 7;
    const int brow = wn * 32 + bri;                  // + na*8
    const int bkc  = bq;

    load_ab(A, W, K, sb, tid, m0, n0, 0, 0);
    CP_WAIT0();
    __syncthreads();

    for (int c = 0; c < NC; c++) {
        const int s = c & 1;
        if (c + 1 < NC) load_ab(A, W, K, sb, tid, m0, n0, c + 1, s ^ 1);

        const uint32_t ahi = sb + s * STAGE_B;
        const uint32_t alo = ahi + 32768;
        const uint32_t whi = ahi + 65536;
#pragma unroll
        for (int ks = 0; ks < 4; ks++) {
            const int kc = ks * 2;
            uint32_t bh[4][2];
            const uint32_t bsw = ((uint32_t)((kc + bkc) ^ bri)) << 4;
#pragma unroll
            for (int na = 0; na < 4; na++)
                ldsm2(bh[na], whi + (brow + na * 8) * 128 + bsw);
            const uint32_t asw = ((uint32_t)((kc + akc) ^ ari)) << 4;
#pragma unroll
            for (int ma = 0; ma < 4; ma++) {
                const uint32_t ra = (arow + ma * 16) * 128 + asw;
                uint32_t ah[4], al[4];
                ldsm4(ah, ahi + ra);
                ldsm4(al, alo + ra);
#pragma unroll
                for (int na = 0; na < 4; na++) {
                    mma16816(acc[ma][na], ah, bh[na]);
                    mma16816(acc[ma][na], al, bh[na]);
                }
            }
        }
        CP_WAIT0();
        __syncthreads();
    }

    // epilogue
    const int lrow = lane >> 2;
    const int lcol = (lane & 3) * 2;
#pragma unroll
    for (int ma = 0; ma < 4; ma++) {
        const int r0 = m0 + wm * 64 + ma * 16 + lrow;
#pragma unroll
        for (int na = 0; na < 4; na++) {
            const int c0 = n0 + wn * 32 + na * 8 + lcol;
            float v0 = acc[ma][na][0] + bias[c0];
            float v1 = acc[ma][na][1] + bias[c0 + 1];
            float v2 = acc[ma][na][2] + bias[c0];
            float v3 = acc[ma][na][3] + bias[c0 + 1];
            if (OUT_MODE == 0) {
                *(float2*)(outF + (size_t)r0 * Ntot + c0)     = make_float2(v0, v1);
                *(float2*)(outF + (size_t)(r0+8) * Ntot + c0) = make_float2(v2, v3);
            } else {
                v0 = gelu_exact(v0); v1 = gelu_exact(v1);
                v2 = gelu_exact(v2); v3 = gelu_exact(v3);
                __half h0,l0,h1,l1,h2,l2,h3,l3;
                hsplit(v0,h0,l0); hsplit(v1,h1,l1);
                hsplit(v2,h2,l2); hsplit(v3,h3,l3);
                {
                    size_t base = (size_t)r0 * 2 * Ntot + c0;
                    *(__half2*)(outS + base)        = __half2{h0,h1};
                    *(__half2*)(outS + base + Ntot) = __half2{l0,l1};
                }
                {
                    size_t base = (size_t)(r0+8) * 2 * Ntot + c0;
                    *(__half2*)(outS + base)        = __half2{h2,h3};
                    *(__half2*)(outS + base + Ntot) = __half2{l2,l3};
                }
            }
        }
    }
}

// ===========================================================================
// Local causal attention (fp32 in, fp16 [hi|lo] split out)
// ===========================================================================
__global__ __launch_bounds__(256)
void attn_kernel(const float* __restrict__ qkv, __half* __restrict__ attns)
{
    const int w    = (blockIdx.x * blockDim.x + threadIdx.x) >> 5;
    const int lane = threadIdx.x & 31;
    if (w >= MTOK * HEADS) return;
    const int m = w / HEADS, h = w - m * HEADS, s = m & (SEQ - 1);

    const float* qp = qkv + (size_t)m * (3 * DIMX) + h * HD;
    const float qa = qp[lane], qb = qp[lane + 32];
    const int jlo = (s >= WIN - 1) ? (s - (WIN - 1)) : 0;
    const int cnt = s - jlo + 1;
    const int mlo = m - (s - jlo);

    float sc[WIN];
#pragma unroll
    for (int t = 0; t < WIN; t++) {
        sc[t] = -3.0e38f;
        if (t < cnt) {
            const float* kp = qkv + (size_t)(mlo + t) * (3 * DIMX) + DIMX + h * HD;
            float d = qa * kp[lane] + qb * kp[lane + 32];
#pragma unroll
            for (int o = 16; o > 0; o >>= 1) d += __shfl_xor_sync(0xffffffffu, d, o);
            sc[t] = d * 0.125f;
        }
    }
    float mx = sc[0];
#pragma unroll
    for (int t = 1; t < WIN; t++) mx = fmaxf(mx, sc[t]);
    float p[WIN], sum = 0.0f;
#pragma unroll
    for (int t = 0; t < WIN; t++) { p[t] = (t < cnt) ? __expf(sc[t] - mx) : 0.0f; sum += p[t]; }
    const float inv = 1.0f / sum;

    float oa = 0.0f, ob = 0.0f;
#pragma unroll
    for (int t = 0; t < WIN; t++) {
        if (t < cnt) {
            const float* vp = qkv + (size_t)(mlo + t) * (3 * DIMX) + 2 * DIMX + h * HD;
            oa = fmaf(p[t], vp[lane], oa);
            ob = fmaf(p[t], vp[lane + 32], ob);
        }
    }
    const size_t base = (size_t)m * 2 * DIMX + h * HD;
    __half hi, lo;
    hsplit(oa * inv, hi, lo);
    attns[base + lane] = hi; attns[base + DIMX + lane] = lo;
    hsplit(ob * inv, hi, lo);
    attns[base + lane + 32] = hi; attns[base + DIMX + lane + 32] = lo;
}

// ===========================================================================
// Residual + LayerNorm (optionally also emit fp16 [hi|lo] split)
// ===========================================================================
template <int SPLIT>
__global__ __launch_bounds__(256)
void ln_residual_kernel(const float* __restrict__ A, const float* __restrict__ Bv,
                        const float* __restrict__ g, const float* __restrict__ beta,
                        float* __restrict__ out, __half* __restrict__ outs)
{
    const int m = blockIdx.x, tid = threadIdx.x;
    const float* a = A  + (size_t)m * DIMX;
    const float* b = Bv + (size_t)m * DIMX;
    float v[4], s = 0.0f, s2 = 0.0f;
#pragma unroll
    for (int i = 0; i < 4; i++) {
        int idx = tid + i * 256;
        v[i] = a[idx] + b[idx];
        s += v[i]; s2 += v[i] * v[i];
    }
#pragma unroll
    for (int o = 16; o > 0; o >>= 1) {
        s  += __shfl_xor_sync(0xffffffffu, s,  o);
        s2 += __shfl_xor_sync(0xffffffffu, s2, o);
    }
    __shared__ float shs[8], shs2[8], shm, shr;
    const int wid = tid >> 5, lane = tid & 31;
    if (lane == 0) { shs[wid] = s; shs2[wid] = s2; }
    __syncthreads();
    if (tid == 0) {
        float S = 0.0f, S2 = 0.0f;
#pragma unroll
        for (int i = 0; i < 8; i++) { S += shs[i]; S2 += shs2[i]; }
        float mean = S * (1.0f / DIMX);
        shm = mean;
        shr = rsqrtf(S2 * (1.0f / DIMX) - mean * mean + EPSLN);
    }
    __syncthreads();
    const float mean = shm, rstd = shr;
#pragma unroll
    for (int i = 0; i < 4; i++) {
        int idx = tid + i * 256;
        float y = (v[i] - mean) * rstd * g[idx] + beta[idx];
        out[(size_t)m * DIMX + idx] = y;
        if (SPLIT) {
            __half hi, lo;
            hsplit(y, hi, lo);
            size_t base = (size_t)m * 2 * DIMX;
            outs[base + idx] = hi;
            outs[base + DIMX + idx] = lo;
        }
    }
}

// ===========================================================================
// kernel_launch
// ===========================================================================
extern "C" void kernel_launch(void* const* d_in, const int* in_sizes, int n_in,
                              void* d_out, int out_size)
{
    const float* x     = (const float*)d_in[0];
    const float* w_in  = (const float*)d_in[1];
    const float* b_in  = (const float*)d_in[2];
    const float* w_out = (const float*)d_in[3];
    const float* b_out = (const float*)d_in[4];
    const float* ln1_g = (const float*)d_in[5];
    const float* ln1_b = (const float*)d_in[6];
    const float* ln2_g = (const float*)d_in[7];
    const float* ln2_b = (const float*)d_in[8];
    const float* w1    = (const float*)d_in[9];
    const float* b1    = (const float*)d_in[10];
    const float* w2    = (const float*)d_in[11];
    const float* b2    = (const float*)d_in[12];
    float* out = (float*)d_out;

    float *qkv, *attnout, *x1, *mlp;
    __half *xs, *attns, *x1s, *hs, *wins, *wouts, *w1s, *w2s;
    cudaGetSymbolAddress((void**)&qkv,     g_qkv);
    cudaGetSymbolAddress((void**)&attnout, g_attnout);
    cudaGetSymbolAddress((void**)&x1,      g_x1);
    cudaGetSymbolAddress((void**)&mlp,     g_mlp);
    cudaGetSymbolAddress((void**)&xs,      g_xs);
    cudaGetSymbolAddress((void**)&attns,   g_attns);
    cudaGetSymbolAddress((void**)&x1s,     g_x1s);
    cudaGetSymbolAddress((void**)&hs,      g_hs);
    cudaGetSymbolAddress((void**)&wins,    g_wins);
    cudaGetSymbolAddress((void**)&wouts,   g_wouts);
    cudaGetSymbolAddress((void**)&w1s,     g_w1s);
    cudaGetSymbolAddress((void**)&w2s,     g_w2s);

    cudaFuncSetAttribute(gemm2_kernel<0>, cudaFuncAttributeMaxDynamicSharedMemorySize, GEMM_SMEM);
    cudaFuncSetAttribute(gemm2_kernel<1>, cudaFuncAttributeMaxDynamicSharedMemorySize, GEMM_SMEM);

    // activation split + weight casts
    conv_split_kernel<<<MTOK * DIMX / 1024, 256>>>(x, xs, DIMX);
    conv_cast_kernel<<<3072 * 1024 / 1024, 256>>>(w_in,  wins);
    conv_cast_kernel<<<1024 * 1024 / 1024, 256>>>(w_out, wouts);
    conv_cast_kernel<<<4096 * 1024 / 1024, 256>>>(w1,    w1s);
    conv_cast_kernel<<<1024 * 4096 / 1024, 256>>>(w2,    w2s);

    // 1. qkv = x @ w_in^T + b_in           [4096, 3072], K=1024
    gemm2_kernel<0><<<dim3(24, 16), 512, GEMM_SMEM>>>(xs, wins, b_in, qkv, nullptr, 3072, 1024);
    // 2. attention -> split
    attn_kernel<<<(MTOK * HEADS * 32) / 256, 256>>>(qkv, attns);
    // 3. attnout = attn @ w_out^T + b_out  [4096, 1024], K=1024
    gemm2_kernel<0><<<dim3(8, 16), 512, GEMM_SMEM>>>(attns, wouts, b_out, attnout, nullptr, 1024, 1024);
    // 4. x1 = LN1(x + attnout), + split
    ln_residual_kernel<1><<<MTOK, 256>>>(x, attnout, ln1_g, ln1_b, x1, x1s);
    // 5. h = gelu(x1 @ w1^T + b1) -> split [4096, 4096], K=1024
    gemm2_kernel<1><<<dim3(32, 16), 512, GEMM_SMEM>>>(x1s, w1s, b1, nullptr, hs, 4096, 1024);
    // 6. mlp = h @ w2^T + b2               [4096, 1024], K=4096
    gemm2_kernel<0><<<dim3(8, 16), 512, GEMM_SMEM>>>(hs, w2s, b2, mlp, nullptr, 1024, 4096);
    // 7. out = LN2(x1 + mlp)
    ln_residual_kernel<0><<<MTOK, 256>>>(x1, mlp, ln2_g, ln2_b, out, nullptr);

    (void)in_sizes; (void)n_in; (void)out_size;
}

// round 10
// speedup vs baseline: 6.5578x; 1.5805x over previous
#include <cuda_runtime.h>
#include <cuda_fp16.h>
#include <math.h>
#include <stdint.h>

#define DIMX   1024
#define HEADS  16
#define HD     64
#define WIN    5
#define SEQ    2048
#define MTOK   4096
#define EPSLN  1e-5f

// ===========================================================================
// PTX helpers (baseline compute_103-safe: cp.async / ldmatrix / mma.sync)
// ===========================================================================
__device__ __forceinline__ uint32_t smem_to_u32(const void* p) {
    uint32_t a;
    asm("{ .reg .u64 t; cvta.to.shared.u64 t, %1; cvt.u32.u64 %0, t; }" : "=r"(a) : "l"(p));
    return a;
}
__device__ __forceinline__ void cp16(uint32_t dst, const void* src) {
    asm volatile("cp.async.cg.shared.global [%0], [%1], 16;" :: "r"(dst), "l"(src) : "memory");
}
#define CP_COMMIT() asm volatile("cp.async.commit_group;" ::: "memory")
#define CP_WAIT0()  asm volatile("cp.async.wait_group 0;"  ::: "memory")
#define CP_WAIT1()  asm volatile("cp.async.wait_group 1;"  ::: "memory")

__device__ __forceinline__ void ldsm4(uint32_t* r, uint32_t addr) {
    asm volatile("ldmatrix.sync.aligned.m8n8.x4.shared.b16 {%0,%1,%2,%3}, [%4];"
        : "=r"(r[0]), "=r"(r[1]), "=r"(r[2]), "=r"(r[3]) : "r"(addr));
}
__device__ __forceinline__ void ldsm2(uint32_t* r, uint32_t addr) {
    asm volatile("ldmatrix.sync.aligned.m8n8.x2.shared.b16 {%0,%1}, [%2];"
        : "=r"(r[0]), "=r"(r[1]) : "r"(addr));
}
__device__ __forceinline__ void mma16816(float* d, const uint32_t* a, const uint32_t* b) {
    asm volatile("mma.sync.aligned.m16n8k16.row.col.f32.f16.f16.f32 "
        "{%0,%1,%2,%3}, {%4,%5,%6,%7}, {%8,%9}, {%0,%1,%2,%3};"
        : "+f"(d[0]), "+f"(d[1]), "+f"(d[2]), "+f"(d[3])
        : "r"(a[0]), "r"(a[1]), "r"(a[2]), "r"(a[3]), "r"(b[0]), "r"(b[1]));
}

// ===========================================================================
// Scratch: all GEMM operands plain fp16 [rows, K]
// ===========================================================================
__device__ __align__(256) float g_qkv    [MTOK * 3 * DIMX];
__device__ __align__(256) float g_attnout[MTOK * DIMX];
__device__ __align__(256) float g_x1     [MTOK * DIMX];
__device__ __align__(256) float g_mlp    [MTOK * DIMX];

__device__ __align__(256) __half g_xs   [MTOK * DIMX];
__device__ __align__(256) __half g_attns[MTOK * DIMX];
__device__ __align__(256) __half g_x1s  [MTOK * DIMX];
__device__ __align__(256) __half g_hs   [MTOK * 4096];
__device__ __align__(256) __half g_wins [3072 * 1024];
__device__ __align__(256) __half g_wouts[1024 * 1024];
__device__ __align__(256) __half g_w1s  [4096 * 1024];
__device__ __align__(256) __half g_w2s  [1024 * 4096];

__device__ __forceinline__ float gelu_exact(float x) {
    return 0.5f * x * (1.0f + erff(x * 0.70710678118654752440f));
}

// ===========================================================================
// fp32 -> fp16 cast
// ===========================================================================
__global__ __launch_bounds__(256)
void conv_cast_kernel(const float* __restrict__ in, __half* __restrict__ out)
{
    size_t idx = (size_t)(blockIdx.x * 256 + threadIdx.x) * 4;
    float4 v = *(const float4*)(in + idx);
    *(__half2*)(out + idx)     = __half2{__float2half_rn(v.x), __float2half_rn(v.y)};
    *(__half2*)(out + idx + 2) = __half2{__float2half_rn(v.z), __float2half_rn(v.w)};
}

// ===========================================================================
// HMMA GEMM: C = A x W^T (+bias), plain fp16 operands, fp32 accum.
// Tile 256x128, 512 threads (16 warps, 4x4), warp tile 64x32.
// K-chunk 64 (128B swizzled rows), 3-stage cp.async pipeline.
// smem stage: A 32K | W 16K = 48K; 3 stages = 144K.
// OUT_MODE 0: fp32 C + bias.  OUT_MODE 1: gelu(C+bias) -> fp16.
// ===========================================================================
#define STAGE_B 49152
#define GEMM_SMEM (3 * STAGE_B)

__device__ __forceinline__ void load_ab(const __half* A, const __half* W,
                                        int K, uint32_t sb, int tid,
                                        int m0, int n0, int c, int s)
{
    const size_t rb = (size_t)2 * K;                 // row bytes (K halves)
    const char* Ab = (const char*)A + (size_t)m0 * rb + (size_t)c * 128;
    const char* Wb = (const char*)W + (size_t)n0 * rb + (size_t)c * 128;
    const uint32_t as = sb + s * STAGE_B;
    const uint32_t ws = as + 32768;
#pragma unroll
    for (int i = 0; i < 4; i++) {                    // A: 256 rows x 128B
        int id = tid + i * 512;
        int r = id >> 3, cb = (id & 7) * 16;
        uint32_t off = (uint32_t)(r * 128 + cb); off ^= (off >> 3) & 0x70;
        cp16(as + off, Ab + (size_t)r * rb + cb);
    }
#pragma unroll
    for (int i = 0; i < 2; i++) {                    // W: 128 rows x 128B
        int id = tid + i * 512;
        int r = id >> 3, cb = (id & 7) * 16;
        uint32_t off = (uint32_t)(r * 128 + cb); off ^= (off >> 3) & 0x70;
        cp16(ws + off, Wb + (size_t)r * rb + cb);
    }
    CP_COMMIT();
}

template <int OUT_MODE>
__global__ __launch_bounds__(512, 1)
void gemm_kernel(const __half* __restrict__ A, const __half* __restrict__ W,
                 const float* __restrict__ bias, float* __restrict__ outF,
                 __half* __restrict__ outS, int Ntot, int K)
{
    extern __shared__ char smem[];
    const uint32_t sb = smem_to_u32(smem);
    const int tid = threadIdx.x, wid = tid >> 5, lane = tid & 31;
    const int wm = wid >> 2, wn = wid & 3;           // 4 x 4 warps
    const int m0 = blockIdx.y * 256, n0 = blockIdx.x * 128;
    const int NC = K / 64;

    float acc[4][4][4];
#pragma unroll
    for (int i = 0; i < 4; i++)
#pragma unroll
        for (int j = 0; j < 4; j++)
#pragma unroll
            for (int q = 0; q < 4; q++) acc[i][j][q] = 0.0f;

    const int aq  = lane >> 3;
    const int ari = lane & 7;
    const int arow = wm * 64 + (aq & 1) * 8 + ari;   // + ma*16
    const int akc  = aq >> 1;
    const int bq   = (lane >> 3) & 1;
    const int bri  = lane & 7;
    const int brow = wn * 32 + bri;                  // + na*8
    const int bkc  = bq;

    load_ab(A, W, K, sb, tid, m0, n0, 0, 0);
    load_ab(A, W, K, sb, tid, m0, n0, 1, 1);

    for (int c = 0; c < NC; c++) {
        if (c + 1 == NC) { CP_WAIT0(); } else { CP_WAIT1(); }
        __syncthreads();
        if (c + 2 < NC) load_ab(A, W, K, sb, tid, m0, n0, c + 2, (c + 2) % 3);

        const int s = c % 3;
        const uint32_t as = sb + s * STAGE_B;
        const uint32_t ws = as + 32768;
#pragma unroll
        for (int ks = 0; ks < 4; ks++) {
            const int kc = ks * 2;
            uint32_t bh[4][2];
            const uint32_t bsw = ((uint32_t)((kc + bkc) ^ bri)) << 4;
#pragma unroll
            for (int na = 0; na < 4; na++)
                ldsm2(bh[na], ws + (brow + na * 8) * 128 + bsw);
            const uint32_t asw = ((uint32_t)((kc + akc) ^ ari)) << 4;
#pragma unroll
            for (int ma = 0; ma < 4; ma++) {
                uint32_t ah[4];
                ldsm4(ah, as + (arow + ma * 16) * 128 + asw);
#pragma unroll
                for (int na = 0; na < 4; na++)
                    mma16816(acc[ma][na], ah, bh[na]);
            }
        }
    }

    // epilogue
    const int lrow = lane >> 2;
    const int lcol = (lane & 3) * 2;
#pragma unroll
    for (int ma = 0; ma < 4; ma++) {
        const int r0 = m0 + wm * 64 + ma * 16 + lrow;
#pragma unroll
        for (int na = 0; na < 4; na++) {
            const int c0 = n0 + wn * 32 + na * 8 + lcol;
            float v0 = acc[ma][na][0] + bias[c0];
            float v1 = acc[ma][na][1] + bias[c0 + 1];
            float v2 = acc[ma][na][2] + bias[c0];
            float v3 = acc[ma][na][3] + bias[c0 + 1];
            if (OUT_MODE == 0) {
                *(float2*)(outF + (size_t)r0 * Ntot + c0)     = make_float2(v0, v1);
                *(float2*)(outF + (size_t)(r0+8) * Ntot + c0) = make_float2(v2, v3);
            } else {
                v0 = gelu_exact(v0); v1 = gelu_exact(v1);
                v2 = gelu_exact(v2); v3 = gelu_exact(v3);
                *(__half2*)(outS + (size_t)r0 * Ntot + c0) =
                    __half2{__float2half_rn(v0), __float2half_rn(v1)};
                *(__half2*)(outS + (size_t)(r0+8) * Ntot + c0) =
                    __half2{__float2half_rn(v2), __float2half_rn(v3)};
            }
        }
    }
}

// ===========================================================================
// Local causal attention (fp32 in, fp16 out)
// ===========================================================================
__global__ __launch_bounds__(256)
void attn_kernel(const float* __restrict__ qkv, __half* __restrict__ attns)
{
    const int w    = (blockIdx.x * blockDim.x + threadIdx.x) >> 5;
    const int lane = threadIdx.x & 31;
    if (w >= MTOK * HEADS) return;
    const int m = w / HEADS, h = w - m * HEADS, s = m & (SEQ - 1);

    const float* qp = qkv + (size_t)m * (3 * DIMX) + h * HD;
    const float qa = qp[lane], qb = qp[lane + 32];
    const int jlo = (s >= WIN - 1) ? (s - (WIN - 1)) : 0;
    const int cnt = s - jlo + 1;
    const int mlo = m - (s - jlo);

    float sc[WIN];
#pragma unroll
    for (int t = 0; t < WIN; t++) {
        sc[t] = -3.0e38f;
        if (t < cnt) {
            const float* kp = qkv + (size_t)(mlo + t) * (3 * DIMX) + DIMX + h * HD;
            float d = qa * kp[lane] + qb * kp[lane + 32];
#pragma unroll
            for (int o = 16; o > 0; o >>= 1) d += __shfl_xor_sync(0xffffffffu, d, o);
            sc[t] = d * 0.125f;
        }
    }
    float mx = sc[0];
#pragma unroll
    for (int t = 1; t < WIN; t++) mx = fmaxf(mx, sc[t]);
    float p[WIN], sum = 0.0f;
#pragma unroll
    for (int t = 0; t < WIN; t++) { p[t] = (t < cnt) ? __expf(sc[t] - mx) : 0.0f; sum += p[t]; }
    const float inv = 1.0f / sum;

    float oa = 0.0f, ob = 0.0f;
#pragma unroll
    for (int t = 0; t < WIN; t++) {
        if (t < cnt) {
            const float* vp = qkv + (size_t)(mlo + t) * (3 * DIMX) + 2 * DIMX + h * HD;
            oa = fmaf(p[t], vp[lane], oa);
            ob = fmaf(p[t], vp[lane + 32], ob);
        }
    }
    const size_t base = (size_t)m * DIMX + h * HD;
    attns[base + lane]      = __float2half_rn(oa * inv);
    attns[base + lane + 32] = __float2half_rn(ob * inv);
}

// ===========================================================================
// Residual + LayerNorm (optionally also emit fp16 cast)
// ===========================================================================
template <int CAST>
__global__ __launch_bounds__(256)
void ln_residual_kernel(const float* __restrict__ A, const float* __restrict__ Bv,
                        const float* __restrict__ g, const float* __restrict__ beta,
                        float* __restrict__ out, __half* __restrict__ outs)
{
    const int m = blockIdx.x, tid = threadIdx.x;
    const float* a = A  + (size_t)m * DIMX;
    const float* b = Bv + (size_t)m * DIMX;
    float v[4], s = 0.0f, s2 = 0.0f;
#pragma unroll
    for (int i = 0; i < 4; i++) {
        int idx = tid + i * 256;
        v[i] = a[idx] + b[idx];
        s += v[i]; s2 += v[i] * v[i];
    }
#pragma unroll
    for (int o = 16; o > 0; o >>= 1) {
        s  += __shfl_xor_sync(0xffffffffu, s,  o);
        s2 += __shfl_xor_sync(0xffffffffu, s2, o);
    }
    __shared__ float shs[8], shs2[8], shm, shr;
    const int wid = tid >> 5, lane = tid & 31;
    if (lane == 0) { shs[wid] = s; shs2[wid] = s2; }
    __syncthreads();
    if (tid == 0) {
        float S = 0.0f, S2 = 0.0f;
#pragma unroll
        for (int i = 0; i < 8; i++) { S += shs[i]; S2 += shs2[i]; }
        float mean = S * (1.0f / DIMX);
        shm = mean;
        shr = rsqrtf(S2 * (1.0f / DIMX) - mean * mean + EPSLN);
    }
    __syncthreads();
    const float mean = shm, rstd = shr;
#pragma unroll
    for (int i = 0; i < 4; i++) {
        int idx = tid + i * 256;
        float y = (v[i] - mean) * rstd * g[idx] + beta[idx];
        out[(size_t)m * DIMX + idx] = y;
        if (CAST) outs[(size_t)m * DIMX + idx] = __float2half_rn(y);
    }
}

// ===========================================================================
// kernel_launch
// ===========================================================================
extern "C" void kernel_launch(void* const* d_in, const int* in_sizes, int n_in,
                              void* d_out, int out_size)
{
    const float* x     = (const float*)d_in[0];
    const float* w_in  = (const float*)d_in[1];
    const float* b_in  = (const float*)d_in[2];
    const float* w_out = (const float*)d_in[3];
    const float* b_out = (const float*)d_in[4];
    const float* ln1_g = (const float*)d_in[5];
    const float* ln1_b = (const float*)d_in[6];
    const float* ln2_g = (const float*)d_in[7];
    const float* ln2_b = (const float*)d_in[8];
    const float* w1    = (const float*)d_in[9];
    const float* b1    = (const float*)d_in[10];
    const float* w2    = (const float*)d_in[11];
    const float* b2    = (const float*)d_in[12];
    float* out = (float*)d_out;

    float *qkv, *attnout, *x1, *mlp;
    __half *xs, *attns, *x1s, *hs, *wins, *wouts, *w1s, *w2s;
    cudaGetSymbolAddress((void**)&qkv,     g_qkv);
    cudaGetSymbolAddress((void**)&attnout, g_attnout);
    cudaGetSymbolAddress((void**)&x1,      g_x1);
    cudaGetSymbolAddress((void**)&mlp,     g_mlp);
    cudaGetSymbolAddress((void**)&xs,      g_xs);
    cudaGetSymbolAddress((void**)&attns,   g_attns);
    cudaGetSymbolAddress((void**)&x1s,     g_x1s);
    cudaGetSymbolAddress((void**)&hs,      g_hs);
    cudaGetSymbolAddress((void**)&wins,    g_wins);
    cudaGetSymbolAddress((void**)&wouts,   g_wouts);
    cudaGetSymbolAddress((void**)&w1s,     g_w1s);
    cudaGetSymbolAddress((void**)&w2s,     g_w2s);

    cudaFuncSetAttribute(gemm_kernel<0>, cudaFuncAttributeMaxDynamicSharedMemorySize, GEMM_SMEM);
    cudaFuncSetAttribute(gemm_kernel<1>, cudaFuncAttributeMaxDynamicSharedMemorySize, GEMM_SMEM);

    // casts
    conv_cast_kernel<<<MTOK * DIMX / 1024, 256>>>(x, xs);
    conv_cast_kernel<<<3072 * 1024 / 1024, 256>>>(w_in,  wins);
    conv_cast_kernel<<<1024 * 1024 / 1024, 256>>>(w_out, wouts);
    conv_cast_kernel<<<4096 * 1024 / 1024, 256>>>(w1,    w1s);
    conv_cast_kernel<<<1024 * 4096 / 1024, 256>>>(w2,    w2s);

    // 1. qkv = x @ w_in^T + b_in           [4096, 3072], K=1024
    gemm_kernel<0><<<dim3(24, 16), 512, GEMM_SMEM>>>(xs, wins, b_in, qkv, nullptr, 3072, 1024);
    // 2. attention -> fp16
    attn_kernel<<<(MTOK * HEADS * 32) / 256, 256>>>(qkv, attns);
    // 3. attnout = attn @ w_out^T + b_out  [4096, 1024], K=1024
    gemm_kernel<0><<<dim3(8, 16), 512, GEMM_SMEM>>>(attns, wouts, b_out, attnout, nullptr, 1024, 1024);
    // 4. x1 = LN1(x + attnout), + fp16 cast
    ln_residual_kernel<1><<<MTOK, 256>>>(x, attnout, ln1_g, ln1_b, x1, x1s);
    // 5. h = gelu(x1 @ w1^T + b1) -> fp16  [4096, 4096], K=1024
    gemm_kernel<1><<<dim3(32, 16), 512, GEMM_SMEM>>>(x1s, w1s, b1, nullptr, hs, 4096, 1024);
    // 6. mlp = h @ w2^T + b2               [4096, 1024], K=4096
    gemm_kernel<0><<<dim3(8, 16), 512, GEMM_SMEM>>>(hs, w2s, b2, mlp, nullptr, 1024, 4096);
    // 7. out = LN2(x1 + mlp)
    ln_residual_kernel<0><<<MTOK, 256>>>(x1, mlp, ln2_g, ln2_b, out, nullptr);

    (void)in_sizes; (void)n_in; (void)out_size;
}

// round 11
// speedup vs baseline: 6.7797x; 1.0338x over previous
#include <cuda_runtime.h>
#include <cuda_fp16.h>
#include <math.h>
#include <stdint.h>

#define DIMX   1024
#define HEADS  16
#define HD     64
#define WIN    5
#define SEQ    2048
#define MTOK   4096
#define EPSLN  1e-5f

// ===========================================================================
// PTX helpers (baseline compute_103-safe: cp.async / ldmatrix / mma.sync)
// ===========================================================================
__device__ __forceinline__ uint32_t smem_to_u32(const void* p) {
    uint32_t a;
    asm("{ .reg .u64 t; cvta.to.shared.u64 t, %1; cvt.u32.u64 %0, t; }" : "=r"(a) : "l"(p));
    return a;
}
__device__ __forceinline__ void cp16(uint32_t dst, const void* src) {
    asm volatile("cp.async.cg.shared.global [%0], [%1], 16;" :: "r"(dst), "l"(src) : "memory");
}
#define CP_COMMIT() asm volatile("cp.async.commit_group;" ::: "memory")
#define CP_WAIT0()  asm volatile("cp.async.wait_group 0;"  ::: "memory")
#define CP_WAIT1()  asm volatile("cp.async.wait_group 1;"  ::: "memory")
#define CP_WAIT2()  asm volatile("cp.async.wait_group 2;"  ::: "memory")

__device__ __forceinline__ void ldsm4(uint32_t* r, uint32_t addr) {
    asm volatile("ldmatrix.sync.aligned.m8n8.x4.shared.b16 {%0,%1,%2,%3}, [%4];"
        : "=r"(r[0]), "=r"(r[1]), "=r"(r[2]), "=r"(r[3]) : "r"(addr));
}
__device__ __forceinline__ void mma16816(float* d, const uint32_t* a, const uint32_t* b) {
    asm volatile("mma.sync.aligned.m16n8k16.row.col.f32.f16.f16.f32 "
        "{%0,%1,%2,%3}, {%4,%5,%6,%7}, {%8,%9}, {%0,%1,%2,%3};"
        : "+f"(d[0]), "+f"(d[1]), "+f"(d[2]), "+f"(d[3])
        : "r"(a[0]), "r"(a[1]), "r"(a[2]), "r"(a[3]), "r"(b[0]), "r"(b[1]));
}

// ===========================================================================
// Scratch: all GEMM operands plain fp16 [rows, K]
// ===========================================================================
__device__ __align__(256) float g_qkv    [MTOK * 3 * DIMX];
__device__ __align__(256) float g_attnout[MTOK * DIMX];
__device__ __align__(256) float g_x1     [MTOK * DIMX];
__device__ __align__(256) float g_mlp    [MTOK * DIMX];

__device__ __align__(256) __half g_xs   [MTOK * DIMX];
__device__ __align__(256) __half g_attns[MTOK * DIMX];
__device__ __align__(256) __half g_x1s  [MTOK * DIMX];
__device__ __align__(256) __half g_hs   [MTOK * 4096];
__device__ __align__(256) __half g_wins [3072 * 1024];
__device__ __align__(256) __half g_wouts[1024 * 1024];
__device__ __align__(256) __half g_w1s  [4096 * 1024];
__device__ __align__(256) __half g_w2s  [1024 * 4096];

__device__ __forceinline__ float gelu_exact(float x) {
    return 0.5f * x * (1.0f + erff(x * 0.70710678118654752440f));
}

// ===========================================================================
// One fused fp32->fp16 cast over all 5 tensors (grid-stride, float4 units)
// Element boundaries: x 4194304 | w_in 3145728 | w_out 1048576 | w1 4194304 | w2 4194304
// ===========================================================================
#define CAST_UNITS 4194304   // 16777216 elements / 4

__global__ __launch_bounds__(256)
void cast_all_kernel(const float* __restrict__ x,   const float* __restrict__ w_in,
                     const float* __restrict__ wo,  const float* __restrict__ w1,
                     const float* __restrict__ w2,
                     __half* __restrict__ xs,   __half* __restrict__ wins,
                     __half* __restrict__ wouts, __half* __restrict__ w1s,
                     __half* __restrict__ w2s)
{
    const unsigned stride = gridDim.x * 256u;
    for (unsigned u = blockIdx.x * 256u + threadIdx.x; u < CAST_UNITS; u += stride) {
        size_t e = (size_t)u * 4;
        const float* in; __half* out; size_t off;
        if      (e <  4194304) { in = x;    out = xs;    off = e; }
        else if (e <  7340032) { in = w_in; out = wins;  off = e - 4194304; }
        else if (e <  8388608) { in = wo;   out = wouts; off = e - 7340032; }
        else if (e < 12582912) { in = w1;   out = w1s;   off = e - 8388608; }
        else                   { in = w2;   out = w2s;   off = e - 12582912; }
        float4 v = *(const float4*)(in + off);
        *(__half2*)(out + off)     = __half2{__float2half_rn(v.x), __float2half_rn(v.y)};
        *(__half2*)(out + off + 2) = __half2{__float2half_rn(v.z), __float2half_rn(v.w)};
    }
}

// ===========================================================================
// HMMA GEMM: C = A x W^T (+bias), fp16 operands, fp32 accum.
// Tile 256x128, 512 threads (16 warps, 4x4), warp tile 64x32.
// K-chunk 64 (128B swizzled rows), 4-stage cp.async pipeline.
// B fetched via 2x ldsm4 (n-atom pairs).  smem: 4 x 48K = 192K.
// OUT_MODE 0: fp32 C + bias.  OUT_MODE 1: gelu(C+bias) -> fp16.
// ===========================================================================
#define STAGE_B 49152
#define GEMM_SMEM (4 * STAGE_B)

__device__ __forceinline__ void load_ab(const __half* A, const __half* W,
                                        int K, uint32_t sb, int tid,
                                        int m0, int n0, int c, int s)
{
    const size_t rb = (size_t)2 * K;                 // row bytes (K halves)
    const char* Ab = (const char*)A + (size_t)m0 * rb + (size_t)c * 128;
    const char* Wb = (const char*)W + (size_t)n0 * rb + (size_t)c * 128;
    const uint32_t as = sb + s * STAGE_B;
    const uint32_t ws = as + 32768;
#pragma unroll
    for (int i = 0; i < 4; i++) {                    // A: 256 rows x 128B
        int id = tid + i * 512;
        int r = id >> 3, cb = (id & 7) * 16;
        uint32_t off = (uint32_t)(r * 128 + cb); off ^= (off >> 3) & 0x70;
        cp16(as + off, Ab + (size_t)r * rb + cb);
    }
#pragma unroll
    for (int i = 0; i < 2; i++) {                    // W: 128 rows x 128B
        int id = tid + i * 512;
        int r = id >> 3, cb = (id & 7) * 16;
        uint32_t off = (uint32_t)(r * 128 + cb); off ^= (off >> 3) & 0x70;
        cp16(ws + off, Wb + (size_t)r * rb + cb);
    }
    CP_COMMIT();
}

template <int OUT_MODE>
__global__ __launch_bounds__(512, 1)
void gemm_kernel(const __half* __restrict__ A, const __half* __restrict__ W,
                 const float* __restrict__ bias, float* __restrict__ outF,
                 __half* __restrict__ outS, int Ntot, int K)
{
    extern __shared__ char smem[];
    const uint32_t sb = smem_to_u32(smem);
    const int tid = threadIdx.x, wid = tid >> 5, lane = tid & 31;
    const int wm = wid >> 2, wn = wid & 3;           // 4 x 4 warps
    const int m0 = blockIdx.y * 256, n0 = blockIdx.x * 128;
    const int NC = K / 64;

    float acc[4][4][4];
#pragma unroll
    for (int i = 0; i < 4; i++)
#pragma unroll
        for (int j = 0; j < 4; j++)
#pragma unroll
            for (int q = 0; q < 4; q++) acc[i][j][q] = 0.0f;

    // A ldsm4: lane q = lane>>3 -> (m-half, k-half)
    const int aq   = lane >> 3;
    const int ari  = lane & 7;
    const int arow = wm * 64 + (aq & 1) * 8 + ari;   // + ma*16
    const int akc  = aq >> 1;
    // B ldsm4: lanes 0-15 -> n-atom 0 (k0,k1), lanes 16-31 -> n-atom 1
    const int bna2 = lane >> 4;                      // 0/1: atom within pair
    const int bq   = (lane >> 3) & 1;                // k-half
    const int bri  = lane & 7;
    const int brow = wn * 32 + bna2 * 8 + bri;       // + pair*16

    load_ab(A, W, K, sb, tid, m0, n0, 0, 0);
    load_ab(A, W, K, sb, tid, m0, n0, 1, 1);
    load_ab(A, W, K, sb, tid, m0, n0, 2, 2);

    for (int c = 0; c < NC; c++) {
        const int rem = NC - 1 - c;
        if (rem >= 2) { CP_WAIT2(); } else if (rem == 1) { CP_WAIT1(); } else { CP_WAIT0(); }
        __syncthreads();
        if (c + 3 < NC) load_ab(A, W, K, sb, tid, m0, n0, c + 3, (c + 3) & 3);

        const int s = c & 3;
        const uint32_t as = sb + s * STAGE_B;
        const uint32_t ws = as + 32768;
#pragma unroll
        for (int ks = 0; ks < 4; ks++) {
            const int kc = ks * 2;
            uint32_t bh[8];                           // frag na: {bh[2na], bh[2na+1]}
            const uint32_t bsw = ((uint32_t)((kc + bq) ^ bri)) << 4;
#pragma unroll
            for (int p = 0; p < 2; p++)
                ldsm4(&bh[4 * p], ws + (brow + p * 16) * 128 + bsw);
            const uint32_t asw = ((uint32_t)((kc + akc) ^ ari)) << 4;
#pragma unroll
            for (int ma = 0; ma < 4; ma++) {
                uint32_t ah[4];
                ldsm4(ah, as + (arow + ma * 16) * 128 + asw);
#pragma unroll
                for (int na = 0; na < 4; na++)
                    mma16816(acc[ma][na], ah, &bh[2 * na]);
            }
        }
    }

    // epilogue
    const int lrow = lane >> 2;
    const int lcol = (lane & 3) * 2;
#pragma unroll
    for (int ma = 0; ma < 4; ma++) {
        const int r0 = m0 + wm * 64 + ma * 16 + lrow;
#pragma unroll
        for (int na = 0; na < 4; na++) {
            const int c0 = n0 + wn * 32 + na * 8 + lcol;
            float v0 = acc[ma][na][0] + bias[c0];
            float v1 = acc[ma][na][1] + bias[c0 + 1];
            float v2 = acc[ma][na][2] + bias[c0];
            float v3 = acc[ma][na][3] + bias[c0 + 1];
            if (OUT_MODE == 0) {
                *(float2*)(outF + (size_t)r0 * Ntot + c0)     = make_float2(v0, v1);
                *(float2*)(outF + (size_t)(r0+8) * Ntot + c0) = make_float2(v2, v3);
            } else {
                v0 = gelu_exact(v0); v1 = gelu_exact(v1);
                v2 = gelu_exact(v2); v3 = gelu_exact(v3);
                *(__half2*)(outS + (size_t)r0 * Ntot + c0) =
                    __half2{__float2half_rn(v0), __float2half_rn(v1)};
                *(__half2*)(outS + (size_t)(r0+8) * Ntot + c0) =
                    __half2{__float2half_rn(v2), __float2half_rn(v3)};
            }
        }
    }
}

// ===========================================================================
// Local causal attention (fp32 in, fp16 out)
// ===========================================================================
__global__ __launch_bounds__(256)
void attn_kernel(const float* __restrict__ qkv, __half* __restrict__ attns)
{
    const int w    = (blockIdx.x * blockDim.x + threadIdx.x) >> 5;
    const int lane = threadIdx.x & 31;
    if (w >= MTOK * HEADS) return;
    const int m = w / HEADS, h = w - m * HEADS, s = m & (SEQ - 1);

    const float* qp = qkv + (size_t)m * (3 * DIMX) + h * HD;
    const float qa = qp[lane], qb = qp[lane + 32];
    const int jlo = (s >= WIN - 1) ? (s - (WIN - 1)) : 0;
    const int cnt = s - jlo + 1;
    const int mlo = m - (s - jlo);

    float sc[WIN];
#pragma unroll
    for (int t = 0; t < WIN; t++) {
        sc[t] = -3.0e38f;
        if (t < cnt) {
            const float* kp = qkv + (size_t)(mlo + t) * (3 * DIMX) + DIMX + h * HD;
            float d = qa * kp[lane] + qb * kp[lane + 32];
#pragma unroll
            for (int o = 16; o > 0; o >>= 1) d += __shfl_xor_sync(0xffffffffu, d, o);
            sc[t] = d * 0.125f;
        }
    }
    float mx = sc[0];
#pragma unroll
    for (int t = 1; t < WIN; t++) mx = fmaxf(mx, sc[t]);
    float p[WIN], sum = 0.0f;
#pragma unroll
    for (int t = 0; t < WIN; t++) { p[t] = (t < cnt) ? __expf(sc[t] - mx) : 0.0f; sum += p[t]; }
    const float inv = 1.0f / sum;

    float oa = 0.0f, ob = 0.0f;
#pragma unroll
    for (int t = 0; t < WIN; t++) {
        if (t < cnt) {
            const float* vp = qkv + (size_t)(mlo + t) * (3 * DIMX) + 2 * DIMX + h * HD;
            oa = fmaf(p[t], vp[lane], oa);
            ob = fmaf(p[t], vp[lane + 32], ob);
        }
    }
    const size_t base = (size_t)m * DIMX + h * HD;
    attns[base + lane]      = __float2half_rn(oa * inv);
    attns[base + lane + 32] = __float2half_rn(ob * inv);
}

// ===========================================================================
// Residual + LayerNorm, float4-vectorized (optionally emit fp16 cast)
// ===========================================================================
template <int CAST>
__global__ __launch_bounds__(256)
void ln_residual_kernel(const float* __restrict__ A, const float* __restrict__ Bv,
                        const float* __restrict__ g, const float* __restrict__ beta,
                        float* __restrict__ out, __half* __restrict__ outs)
{
    const int m = blockIdx.x, tid = threadIdx.x;
    const float4* a4 = (const float4*)(A  + (size_t)m * DIMX);
    const float4* b4 = (const float4*)(Bv + (size_t)m * DIMX);

    float4 av = a4[tid], bv = b4[tid];
    float4 v = make_float4(av.x + bv.x, av.y + bv.y, av.z + bv.z, av.w + bv.w);
    float s  = v.x + v.y + v.z + v.w;
    float s2 = v.x*v.x + v.y*v.y + v.z*v.z + v.w*v.w;
#pragma unroll
    for (int o = 16; o > 0; o >>= 1) {
        s  += __shfl_xor_sync(0xffffffffu, s,  o);
        s2 += __shfl_xor_sync(0xffffffffu, s2, o);
    }
    __shared__ float shs[8], shs2[8], shm, shr;
    const int wid = tid >> 5, lane = tid & 31;
    if (lane == 0) { shs[wid] = s; shs2[wid] = s2; }
    __syncthreads();
    if (tid == 0) {
        float S = 0.0f, S2 = 0.0f;
#pragma unroll
        for (int i = 0; i < 8; i++) { S += shs[i]; S2 += shs2[i]; }
        float mean = S * (1.0f / DIMX);
        shm = mean;
        shr = rsqrtf(S2 * (1.0f / DIMX) - mean * mean + EPSLN);
    }
    __syncthreads();
    const float mean = shm, rstd = shr;
    float4 gv = ((const float4*)g)[tid];
    float4 be = ((const float4*)beta)[tid];
    float4 y;
    y.x = (v.x - mean) * rstd * gv.x + be.x;
    y.y = (v.y - mean) * rstd * gv.y + be.y;
    y.z = (v.z - mean) * rstd * gv.z + be.z;
    y.w = (v.w - mean) * rstd * gv.w + be.w;
    ((float4*)(out + (size_t)m * DIMX))[tid] = y;
    if (CAST) {
        __half2* o2 = (__half2*)(outs + (size_t)m * DIMX + tid * 4);
        o2[0] = __half2{__float2half_rn(y.x), __float2half_rn(y.y)};
        o2[1] = __half2{__float2half_rn(y.z), __float2half_rn(y.w)};
    }
}

// ===========================================================================
// kernel_launch
// ===========================================================================
extern "C" void kernel_launch(void* const* d_in, const int* in_sizes, int n_in,
                              void* d_out, int out_size)
{
    const float* x     = (const float*)d_in[0];
    const float* w_in  = (const float*)d_in[1];
    const float* b_in  = (const float*)d_in[2];
    const float* w_out = (const float*)d_in[3];
    const float* b_out = (const float*)d_in[4];
    const float* ln1_g = (const float*)d_in[5];
    const float* ln1_b = (const float*)d_in[6];
    const float* ln2_g = (const float*)d_in[7];
    const float* ln2_b = (const float*)d_in[8];
    const float* w1    = (const float*)d_in[9];
    const float* b1    = (const float*)d_in[10];
    const float* w2    = (const float*)d_in[11];
    const float* b2    = (const float*)d_in[12];
    float* out = (float*)d_out;

    float *qkv, *attnout, *x1, *mlp;
    __half *xs, *attns, *x1s, *hs, *wins, *wouts, *w1s, *w2s;
    cudaGetSymbolAddress((void**)&qkv,     g_qkv);
    cudaGetSymbolAddress((void**)&attnout, g_attnout);
    cudaGetSymbolAddress((void**)&x1,      g_x1);
    cudaGetSymbolAddress((void**)&mlp,     g_mlp);
    cudaGetSymbolAddress((void**)&xs,      g_xs);
    cudaGetSymbolAddress((void**)&attns,   g_attns);
    cudaGetSymbolAddress((void**)&x1s,     g_x1s);
    cudaGetSymbolAddress((void**)&hs,      g_hs);
    cudaGetSymbolAddress((void**)&wins,    g_wins);
    cudaGetSymbolAddress((void**)&wouts,   g_wouts);
    cudaGetSymbolAddress((void**)&w1s,     g_w1s);
    cudaGetSymbolAddress((void**)&w2s,     g_w2s);

    cudaFuncSetAttribute(gemm_kernel<0>, cudaFuncAttributeMaxDynamicSharedMemorySize, GEMM_SMEM);
    cudaFuncSetAttribute(gemm_kernel<1>, cudaFuncAttributeMaxDynamicSharedMemorySize, GEMM_SMEM);

    // 0. all fp32 -> fp16 casts in one launch
    cast_all_kernel<<<8192, 256>>>(x, w_in, w_out, w1, w2, xs, wins, wouts, w1s, w2s);

    // 1. qkv = x @ w_in^T + b_in           [4096, 3072], K=1024
    gemm_kernel<0><<<dim3(24, 16), 512, GEMM_SMEM>>>(xs, wins, b_in, qkv, nullptr, 3072, 1024);
    // 2. attention -> fp16
    attn_kernel<<<(MTOK * HEADS * 32) / 256, 256>>>(qkv, attns);
    // 3. attnout = attn @ w_out^T + b_out  [4096, 1024], K=1024
    gemm_kernel<0><<<dim3(8, 16), 512, GEMM_SMEM>>>(attns, wouts, b_out, attnout, nullptr, 1024, 1024);
    // 4. x1 = LN1(x + attnout), + fp16 cast
    ln_residual_kernel<1><<<MTOK, 256>>>(x, attnout, ln1_g, ln1_b, x1, x1s);
    // 5. h = gelu(x1 @ w1^T + b1) -> fp16  [4096, 4096], K=1024
    gemm_kernel<1><<<dim3(32, 16), 512, GEMM_SMEM>>>(x1s, w1s, b1, nullptr, hs, 4096, 1024);
    // 6. mlp = h @ w2^T + b2               [4096, 1024], K=4096
    gemm_kernel<0><<<dim3(8, 16), 512, GEMM_SMEM>>>(hs, w2s, b2, mlp, nullptr, 1024, 4096);
    // 7. out = LN2(x1 + mlp)
    ln_residual_kernel<0><<<MTOK, 256>>>(x1, mlp, ln2_g, ln2_b, out, nullptr);

    (void)in_sizes; (void)n_in; (void)out_size;
}

// round 12
// speedup vs baseline: 7.1987x; 1.0618x over previous
#include <cuda_runtime.h>
#include <cuda_fp16.h>
#include <math.h>
#include <stdint.h>

#define DIMX   1024
#define HEADS  16
#define HD     64
#define WIN    5
#define SEQ    2048
#define MTOK   4096
#define EPSLN  1e-5f

// ===========================================================================
// PTX helpers (baseline compute_103-safe: cp.async / ldmatrix / mma.sync)
// ===========================================================================
__device__ __forceinline__ uint32_t smem_to_u32(const void* p) {
    uint32_t a;
    asm("{ .reg .u64 t; cvta.to.shared.u64 t, %1; cvt.u32.u64 %0, t; }" : "=r"(a) : "l"(p));
    return a;
}
__device__ __forceinline__ void cp16(uint32_t dst, const void* src) {
    asm volatile("cp.async.cg.shared.global [%0], [%1], 16;" :: "r"(dst), "l"(src) : "memory");
}
#define CP_COMMIT() asm volatile("cp.async.commit_group;" ::: "memory")
#define CP_WAIT0()  asm volatile("cp.async.wait_group 0;"  ::: "memory")
#define CP_WAIT1()  asm volatile("cp.async.wait_group 1;"  ::: "memory")

__device__ __forceinline__ void ldsm4(uint32_t* r, uint32_t addr) {
    asm volatile("ldmatrix.sync.aligned.m8n8.x4.shared.b16 {%0,%1,%2,%3}, [%4];"
        : "=r"(r[0]), "=r"(r[1]), "=r"(r[2]), "=r"(r[3]) : "r"(addr));
}
__device__ __forceinline__ void mma16816(float* d, const uint32_t* a, const uint32_t* b) {
    asm volatile("mma.sync.aligned.m16n8k16.row.col.f32.f16.f16.f32 "
        "{%0,%1,%2,%3}, {%4,%5,%6,%7}, {%8,%9}, {%0,%1,%2,%3};"
        : "+f"(d[0]), "+f"(d[1]), "+f"(d[2]), "+f"(d[3])
        : "r"(a[0]), "r"(a[1]), "r"(a[2]), "r"(a[3]), "r"(b[0]), "r"(b[1]));
}

// ===========================================================================
// Scratch: all GEMM operands plain fp16 [rows, K]
// ===========================================================================
__device__ __align__(256) float g_qkv    [MTOK * 3 * DIMX];
__device__ __align__(256) float g_attnout[MTOK * DIMX];
__device__ __align__(256) float g_x1     [MTOK * DIMX];
__device__ __align__(256) float g_mlp    [MTOK * DIMX];

__device__ __align__(256) __half g_xs   [MTOK * DIMX];
__device__ __align__(256) __half g_attns[MTOK * DIMX];
__device__ __align__(256) __half g_x1s  [MTOK * DIMX];
__device__ __align__(256) __half g_hs   [MTOK * 4096];
__device__ __align__(256) __half g_wins [3072 * 1024];
__device__ __align__(256) __half g_wouts[1024 * 1024];
__device__ __align__(256) __half g_w1s  [4096 * 1024];
__device__ __align__(256) __half g_w2s  [1024 * 4096];

__device__ __forceinline__ float gelu_exact(float x) {
    return 0.5f * x * (1.0f + erff(x * 0.70710678118654752440f));
}

// ===========================================================================
// One fused fp32->fp16 cast over all 5 tensors (grid-stride, float4 units)
// ===========================================================================
#define CAST_UNITS 4194304   // 16777216 elements / 4

__global__ __launch_bounds__(256)
void cast_all_kernel(const float* __restrict__ x,   const float* __restrict__ w_in,
                     const float* __restrict__ wo,  const float* __restrict__ w1,
                     const float* __restrict__ w2,
                     __half* __restrict__ xs,   __half* __restrict__ wins,
                     __half* __restrict__ wouts, __half* __restrict__ w1s,
                     __half* __restrict__ w2s)
{
    const unsigned stride = gridDim.x * 256u;
    for (unsigned u = blockIdx.x * 256u + threadIdx.x; u < CAST_UNITS; u += stride) {
        size_t e = (size_t)u * 4;
        const float* in; __half* out; size_t off;
        if      (e <  4194304) { in = x;    out = xs;    off = e; }
        else if (e <  7340032) { in = w_in; out = wins;  off = e - 4194304; }
        else if (e <  8388608) { in = wo;   out = wouts; off = e - 7340032; }
        else if (e < 12582912) { in = w1;   out = w1s;   off = e - 8388608; }
        else                   { in = w2;   out = w2s;   off = e - 12582912; }
        float4 v = *(const float4*)(in + off);
        *(__half2*)(out + off)     = __half2{__float2half_rn(v.x), __float2half_rn(v.y)};
        *(__half2*)(out + off + 2) = __half2{__float2half_rn(v.z), __float2half_rn(v.w)};
    }
}

// ===========================================================================
// HMMA GEMM: C = A x W^T (+bias), fp16 operands, fp32 accum.
// Tile 128x128, 256 threads (8 warps, 2x4), warp tile 64x32, 2 CTAs/SM.
// K-chunk 64 (128B swizzled rows), 3-stage cp.async pipeline.
// smem: 3 x 32K = 96K per CTA -> 192K/SM with 2 CTAs.
// OUT_MODE 0: fp32 C + bias.  OUT_MODE 1: gelu(C+bias) -> fp16.
// ===========================================================================
#define STAGE_B 32768
#define GEMM_SMEM (3 * STAGE_B)

__device__ __forceinline__ void load_ab(const __half* A, const __half* W,
                                        int K, uint32_t sb, int tid,
                                        int m0, int n0, int c, int s)
{
    const size_t rb = (size_t)2 * K;                 // row bytes (K halves)
    const char* Ab = (const char*)A + (size_t)m0 * rb + (size_t)c * 128;
    const char* Wb = (const char*)W + (size_t)n0 * rb + (size_t)c * 128;
    const uint32_t as = sb + s * STAGE_B;
    const uint32_t ws = as + 16384;
#pragma unroll
    for (int i = 0; i < 4; i++) {                    // A: 128 rows x 128B
        int id = tid + i * 256;
        int r = id >> 3, cb = (id & 7) * 16;
        uint32_t off = (uint32_t)(r * 128 + cb); off ^= (off >> 3) & 0x70;
        cp16(as + off, Ab + (size_t)r * rb + cb);
    }
#pragma unroll
    for (int i = 0; i < 4; i++) {                    // W: 128 rows x 128B
        int id = tid + i * 256;
        int r = id >> 3, cb = (id & 7) * 16;
        uint32_t off = (uint32_t)(r * 128 + cb); off ^= (off >> 3) & 0x70;
        cp16(ws + off, Wb + (size_t)r * rb + cb);
    }
    CP_COMMIT();
}

template <int OUT_MODE>
__global__ __launch_bounds__(256, 2)
void gemm_kernel(const __half* __restrict__ A, const __half* __restrict__ W,
                 const float* __restrict__ bias, float* __restrict__ outF,
                 __half* __restrict__ outS, int Ntot, int K)
{
    extern __shared__ char smem[];
    const uint32_t sb = smem_to_u32(smem);
    const int tid = threadIdx.x, wid = tid >> 5, lane = tid & 31;
    const int wm = wid >> 2, wn = wid & 3;           // 2 x 4 warps
    const int m0 = blockIdx.y * 128, n0 = blockIdx.x * 128;
    const int NC = K / 64;

    float acc[4][4][4];
#pragma unroll
    for (int i = 0; i < 4; i++)
#pragma unroll
        for (int j = 0; j < 4; j++)
#pragma unroll
            for (int q = 0; q < 4; q++) acc[i][j][q] = 0.0f;

    // A ldsm4: lane q = lane>>3 -> (m-half, k-half)
    const int aq   = lane >> 3;
    const int ari  = lane & 7;
    const int arow = wm * 64 + (aq & 1) * 8 + ari;   // + ma*16
    const int akc  = aq >> 1;
    // B ldsm4: lanes 0-15 -> n-atom 0 (k0,k1), lanes 16-31 -> n-atom 1
    const int bna2 = lane >> 4;
    const int bq   = (lane >> 3) & 1;
    const int bri  = lane & 7;
    const int brow = wn * 32 + bna2 * 8 + bri;       // + pair*16

    load_ab(A, W, K, sb, tid, m0, n0, 0, 0);
    load_ab(A, W, K, sb, tid, m0, n0, 1, 1);

    for (int c = 0; c < NC; c++) {
        if (c + 1 == NC) { CP_WAIT0(); } else { CP_WAIT1(); }
        __syncthreads();
        if (c + 2 < NC) load_ab(A, W, K, sb, tid, m0, n0, c + 2, (c + 2) % 3);

        const int s = c % 3;
        const uint32_t as = sb + s * STAGE_B;
        const uint32_t ws = as + 16384;
#pragma unroll
        for (int ks = 0; ks < 4; ks++) {
            const int kc = ks * 2;
            uint32_t bh[8];                           // frag na: {bh[2na], bh[2na+1]}
            const uint32_t bsw = ((uint32_t)((kc + bq) ^ bri)) << 4;
#pragma unroll
            for (int p = 0; p < 2; p++)
                ldsm4(&bh[4 * p], ws + (brow + p * 16) * 128 + bsw);
            const uint32_t asw = ((uint32_t)((kc + akc) ^ ari)) << 4;
#pragma unroll
            for (int ma = 0; ma < 4; ma++) {
                uint32_t ah[4];
                ldsm4(ah, as + (arow + ma * 16) * 128 + asw);
#pragma unroll
                for (int na = 0; na < 4; na++)
                    mma16816(acc[ma][na], ah, &bh[2 * na]);
            }
        }
    }

    // epilogue
    const int lrow = lane >> 2;
    const int lcol = (lane & 3) * 2;
#pragma unroll
    for (int ma = 0; ma < 4; ma++) {
        const int r0 = m0 + wm * 64 + ma * 16 + lrow;
#pragma unroll
        for (int na = 0; na < 4; na++) {
            const int c0 = n0 + wn * 32 + na * 8 + lcol;
            float v0 = acc[ma][na][0] + bias[c0];
            float v1 = acc[ma][na][1] + bias[c0 + 1];
            float v2 = acc[ma][na][2] + bias[c0];
            float v3 = acc[ma][na][3] + bias[c0 + 1];
            if (OUT_MODE == 0) {
                *(float2*)(outF + (size_t)r0 * Ntot + c0)     = make_float2(v0, v1);
                *(float2*)(outF + (size_t)(r0+8) * Ntot + c0) = make_float2(v2, v3);
            } else {
                v0 = gelu_exact(v0); v1 = gelu_exact(v1);
                v2 = gelu_exact(v2); v3 = gelu_exact(v3);
                *(__half2*)(outS + (size_t)r0 * Ntot + c0) =
                    __half2{__float2half_rn(v0), __float2half_rn(v1)};
                *(__half2*)(outS + (size_t)(r0+8) * Ntot + c0) =
                    __half2{__float2half_rn(v2), __float2half_rn(v3)};
            }
        }
    }
}

// ===========================================================================
// Local causal attention (fp32 in, fp16 out)
// ===========================================================================
__global__ __launch_bounds__(256)
void attn_kernel(const float* __restrict__ qkv, __half* __restrict__ attns)
{
    const int w    = (blockIdx.x * blockDim.x + threadIdx.x) >> 5;
    const int lane = threadIdx.x & 31;
    if (w >= MTOK * HEADS) return;
    const int m = w / HEADS, h = w - m * HEADS, s = m & (SEQ - 1);

    const float* qp = qkv + (size_t)m * (3 * DIMX) + h * HD;
    const float qa = qp[lane], qb = qp[lane + 32];
    const int jlo = (s >= WIN - 1) ? (s - (WIN - 1)) : 0;
    const int cnt = s - jlo + 1;
    const int mlo = m - (s - jlo);

    float sc[WIN];
#pragma unroll
    for (int t = 0; t < WIN; t++) {
        sc[t] = -3.0e38f;
        if (t < cnt) {
            const float* kp = qkv + (size_t)(mlo + t) * (3 * DIMX) + DIMX + h * HD;
            float d = qa * kp[lane] + qb * kp[lane + 32];
#pragma unroll
            for (int o = 16; o > 0; o >>= 1) d += __shfl_xor_sync(0xffffffffu, d, o);
            sc[t] = d * 0.125f;
        }
    }
    float mx = sc[0];
#pragma unroll
    for (int t = 1; t < WIN; t++) mx = fmaxf(mx, sc[t]);
    float p[WIN], sum = 0.0f;
#pragma unroll
    for (int t = 0; t < WIN; t++) { p[t] = (t < cnt) ? __expf(sc[t] - mx) : 0.0f; sum += p[t]; }
    const float inv = 1.0f / sum;

    float oa = 0.0f, ob = 0.0f;
#pragma unroll
    for (int t = 0; t < WIN; t++) {
        if (t < cnt) {
            const float* vp = qkv + (size_t)(mlo + t) * (3 * DIMX) + 2 * DIMX + h * HD;
            oa = fmaf(p[t], vp[lane], oa);
            ob = fmaf(p[t], vp[lane + 32], ob);
        }
    }
    const size_t base = (size_t)m * DIMX + h * HD;
    attns[base + lane]      = __float2half_rn(oa * inv);
    attns[base + lane + 32] = __float2half_rn(ob * inv);
}

// ===========================================================================
// Residual + LayerNorm, float4-vectorized (optionally emit fp16 cast)
// ===========================================================================
template <int CAST>
__global__ __launch_bounds__(256)
void ln_residual_kernel(const float* __restrict__ A, const float* __restrict__ Bv,
                        const float* __restrict__ g, const float* __restrict__ beta,
                        float* __restrict__ out, __half* __restrict__ outs)
{
    const int m = blockIdx.x, tid = threadIdx.x;
    const float4* a4 = (const float4*)(A  + (size_t)m * DIMX);
    const float4* b4 = (const float4*)(Bv + (size_t)m * DIMX);

    float4 av = a4[tid], bv = b4[tid];
    float4 v = make_float4(av.x + bv.x, av.y + bv.y, av.z + bv.z, av.w + bv.w);
    float s  = v.x + v.y + v.z + v.w;
    float s2 = v.x*v.x + v.y*v.y + v.z*v.z + v.w*v.w;
#pragma unroll
    for (int o = 16; o > 0; o >>= 1) {
        s  += __shfl_xor_sync(0xffffffffu, s,  o);
        s2 += __shfl_xor_sync(0xffffffffu, s2, o);
    }
    __shared__ float shs[8], shs2[8], shm, shr;
    const int wid = tid >> 5, lane = tid & 31;
    if (lane == 0) { shs[wid] = s; shs2[wid] = s2; }
    __syncthreads();
    if (tid == 0) {
        float S = 0.0f, S2 = 0.0f;
#pragma unroll
        for (int i = 0; i < 8; i++) { S += shs[i]; S2 += shs2[i]; }
        float mean = S * (1.0f / DIMX);
        shm = mean;
        shr = rsqrtf(S2 * (1.0f / DIMX) - mean * mean + EPSLN);
    }
    __syncthreads();
    const float mean = shm, rstd = shr;
    float4 gv = ((const float4*)g)[tid];
    float4 be = ((const float4*)beta)[tid];
    float4 y;
    y.x = (v.x - mean) * rstd * gv.x + be.x;
    y.y = (v.y - mean) * rstd * gv.y + be.y;
    y.z = (v.z - mean) * rstd * gv.z + be.z;
    y.w = (v.w - mean) * rstd * gv.w + be.w;
    ((float4*)(out + (size_t)m * DIMX))[tid] = y;
    if (CAST) {
        __half2* o2 = (__half2*)(outs + (size_t)m * DIMX + tid * 4);
        o2[0] = __half2{__float2half_rn(y.x), __float2half_rn(y.y)};
        o2[1] = __half2{__float2half_rn(y.z), __float2half_rn(y.w)};
    }
}

// ===========================================================================
// kernel_launch
// ===========================================================================
extern "C" void kernel_launch(void* const* d_in, const int* in_sizes, int n_in,
                              void* d_out, int out_size)
{
    const float* x     = (const float*)d_in[0];
    const float* w_in  = (const float*)d_in[1];
    const float* b_in  = (const float*)d_in[2];
    const float* w_out = (const float*)d_in[3];
    const float* b_out = (const float*)d_in[4];
    const float* ln1_g = (const float*)d_in[5];
    const float* ln1_b = (const float*)d_in[6];
    const float* ln2_g = (const float*)d_in[7];
    const float* ln2_b = (const float*)d_in[8];
    const float* w1    = (const float*)d_in[9];
    const float* b1    = (const float*)d_in[10];
    const float* w2    = (const float*)d_in[11];
    const float* b2    = (const float*)d_in[12];
    float* out = (float*)d_out;

    float *qkv, *attnout, *x1, *mlp;
    __half *xs, *attns, *x1s, *hs, *wins, *wouts, *w1s, *w2s;
    cudaGetSymbolAddress((void**)&qkv,     g_qkv);
    cudaGetSymbolAddress((void**)&attnout, g_attnout);
    cudaGetSymbolAddress((void**)&x1,      g_x1);
    cudaGetSymbolAddress((void**)&mlp,     g_mlp);
    cudaGetSymbolAddress((void**)&xs,      g_xs);
    cudaGetSymbolAddress((void**)&attns,   g_attns);
    cudaGetSymbolAddress((void**)&x1s,     g_x1s);
    cudaGetSymbolAddress((void**)&hs,      g_hs);
    cudaGetSymbolAddress((void**)&wins,    g_wins);
    cudaGetSymbolAddress((void**)&wouts,   g_wouts);
    cudaGetSymbolAddress((void**)&w1s,     g_w1s);
    cudaGetSymbolAddress((void**)&w2s,     g_w2s);

    cudaFuncSetAttribute(gemm_kernel<0>, cudaFuncAttributeMaxDynamicSharedMemorySize, GEMM_SMEM);
    cudaFuncSetAttribute(gemm_kernel<1>, cudaFuncAttributeMaxDynamicSharedMemorySize, GEMM_SMEM);

    // 0. all fp32 -> fp16 casts in one launch
    cast_all_kernel<<<8192, 256>>>(x, w_in, w_out, w1, w2, xs, wins, wouts, w1s, w2s);

    // 1. qkv = x @ w_in^T + b_in           [4096, 3072], K=1024
    gemm_kernel<0><<<dim3(24, 32), 256, GEMM_SMEM>>>(xs, wins, b_in, qkv, nullptr, 3072, 1024);
    // 2. attention -> fp16
    attn_kernel<<<(MTOK * HEADS * 32) / 256, 256>>>(qkv, attns);
    // 3. attnout = attn @ w_out^T + b_out  [4096, 1024], K=1024
    gemm_kernel<0><<<dim3(8, 32), 256, GEMM_SMEM>>>(attns, wouts, b_out, attnout, nullptr, 1024, 1024);
    // 4. x1 = LN1(x + attnout), + fp16 cast
    ln_residual_kernel<1><<<MTOK, 256>>>(x, attnout, ln1_g, ln1_b, x1, x1s);
    // 5. h = gelu(x1 @ w1^T + b1) -> fp16  [4096, 4096], K=1024
    gemm_kernel<1><<<dim3(32, 32), 256, GEMM_SMEM>>>(x1s, w1s, b1, nullptr, hs, 4096, 1024);
    // 6. mlp = h @ w2^T + b2               [4096, 1024], K=4096
    gemm_kernel<0><<<dim3(8, 32), 256, GEMM_SMEM>>>(hs, w2s, b2, mlp, nullptr, 1024, 4096);
    // 7. out = LN2(x1 + mlp)
    ln_residual_kernel<0><<<MTOK, 256>>>(x1, mlp, ln2_g, ln2_b, out, nullptr);

    (void)in_sizes; (void)n_in; (void)out_size;
}

// round 13
// speedup vs baseline: 7.3601x; 1.0224x over previous
#include <cuda_runtime.h>
#include <cuda_fp16.h>
#include <math.h>
#include <stdint.h>

#define DIMX   1024
#define HEADS  16
#define HD     64
#define WIN    5
#define SEQ    2048
#define MTOK   4096
#define EPSLN  1e-5f

// ===========================================================================
// PTX helpers (baseline compute_103-safe: cp.async / ldmatrix / mma.sync)
// ===========================================================================
__device__ __forceinline__ uint32_t smem_to_u32(const void* p) {
    uint32_t a;
    asm("{ .reg .u64 t; cvta.to.shared.u64 t, %1; cvt.u32.u64 %0, t; }" : "=r"(a) : "l"(p));
    return a;
}
__device__ __forceinline__ void cp16(uint32_t dst, const void* src) {
    asm volatile("cp.async.cg.shared.global [%0], [%1], 16;" :: "r"(dst), "l"(src) : "memory");
}
#define CP_COMMIT() asm volatile("cp.async.commit_group;" ::: "memory")
#define CP_WAIT0()  asm volatile("cp.async.wait_group 0;"  ::: "memory")
#define CP_WAIT1()  asm volatile("cp.async.wait_group 1;"  ::: "memory")

__device__ __forceinline__ void ldsm4(uint32_t* r, uint32_t addr) {
    asm volatile("ldmatrix.sync.aligned.m8n8.x4.shared.b16 {%0,%1,%2,%3}, [%4];"
        : "=r"(r[0]), "=r"(r[1]), "=r"(r[2]), "=r"(r[3]) : "r"(addr));
}
__device__ __forceinline__ void mma16816(float* d, const uint32_t* a, const uint32_t* b) {
    asm volatile("mma.sync.aligned.m16n8k16.row.col.f32.f16.f16.f32 "
        "{%0,%1,%2,%3}, {%4,%5,%6,%7}, {%8,%9}, {%0,%1,%2,%3};"
        : "+f"(d[0]), "+f"(d[1]), "+f"(d[2]), "+f"(d[3])
        : "r"(a[0]), "r"(a[1]), "r"(a[2]), "r"(a[3]), "r"(b[0]), "r"(b[1]));
}

// ===========================================================================
// Scratch: all GEMM operands plain fp16 [rows, K]
// ===========================================================================
__device__ __align__(256) float g_qkv    [MTOK * 3 * DIMX];
__device__ __align__(256) float g_attnout[MTOK * DIMX];
__device__ __align__(256) float g_x1     [MTOK * DIMX];
__device__ __align__(256) float g_mlp    [MTOK * DIMX];

__device__ __align__(256) __half g_xs   [MTOK * DIMX];
__device__ __align__(256) __half g_attns[MTOK * DIMX];
__device__ __align__(256) __half g_x1s  [MTOK * DIMX];
__device__ __align__(256) __half g_hs   [MTOK * 4096];
__device__ __align__(256) __half g_wins [3072 * 1024];
__device__ __align__(256) __half g_wouts[1024 * 1024];
__device__ __align__(256) __half g_w1s  [4096 * 1024];
__device__ __align__(256) __half g_w2s  [1024 * 4096];

__device__ __forceinline__ float gelu_exact(float x) {
    return 0.5f * x * (1.0f + erff(x * 0.70710678118654752440f));
}

// ===========================================================================
// One fused fp32->fp16 cast over all 5 tensors (grid-stride, float4 units)
// ===========================================================================
#define CAST_UNITS 4194304   // 16777216 elements / 4

__global__ __launch_bounds__(256)
void cast_all_kernel(const float* __restrict__ x,   const float* __restrict__ w_in,
                     const float* __restrict__ wo,  const float* __restrict__ w1,
                     const float* __restrict__ w2,
                     __half* __restrict__ xs,   __half* __restrict__ wins,
                     __half* __restrict__ wouts, __half* __restrict__ w1s,
                     __half* __restrict__ w2s)
{
    const unsigned stride = gridDim.x * 256u;
    for (unsigned u = blockIdx.x * 256u + threadIdx.x; u < CAST_UNITS; u += stride) {
        size_t e = (size_t)u * 4;
        const float* in; __half* out; size_t off;
        if      (e <  4194304) { in = x;    out = xs;    off = e; }
        else if (e <  7340032) { in = w_in; out = wins;  off = e - 4194304; }
        else if (e <  8388608) { in = wo;   out = wouts; off = e - 7340032; }
        else if (e < 12582912) { in = w1;   out = w1s;   off = e - 8388608; }
        else                   { in = w2;   out = w2s;   off = e - 12582912; }
        float4 v = *(const float4*)(in + off);
        *(__half2*)(out + off)     = __half2{__float2half_rn(v.x), __float2half_rn(v.y)};
        *(__half2*)(out + off + 2) = __half2{__float2half_rn(v.z), __float2half_rn(v.w)};
    }
}

// ===========================================================================
// HMMA GEMM: C = A x W^T (+bias), fp16 operands, fp32 accum.
// Tile 128x128, 128 threads (4 warps, 2x2), warp tile 64x64, 2 CTAs/SM.
// K-chunk 64 (128B swizzled rows), 3-stage cp.async pipeline.
// smem: 3 x 32K = 96K per CTA -> 192K/SM with 2 CTAs.
// OUT_MODE 0: fp32 C + bias.  OUT_MODE 1: gelu(C+bias) -> fp16.
// ===========================================================================
#define STAGE_B 32768
#define GEMM_SMEM (3 * STAGE_B)

__device__ __forceinline__ void load_ab(const __half* A, const __half* W,
                                        int K, uint32_t sb, int tid,
                                        int m0, int n0, int c, int s)
{
    const size_t rb = (size_t)2 * K;                 // row bytes (K halves)
    const char* Ab = (const char*)A + (size_t)m0 * rb + (size_t)c * 128;
    const char* Wb = (const char*)W + (size_t)n0 * rb + (size_t)c * 128;
    const uint32_t as = sb + s * STAGE_B;
    const uint32_t ws = as + 16384;
#pragma unroll
    for (int i = 0; i < 8; i++) {                    // A: 128 rows x 128B
        int id = tid + i * 128;
        int r = id >> 3, cb = (id & 7) * 16;
        uint32_t off = (uint32_t)(r * 128 + cb); off ^= (off >> 3) & 0x70;
        cp16(as + off, Ab + (size_t)r * rb + cb);
    }
#pragma unroll
    for (int i = 0; i < 8; i++) {                    // W: 128 rows x 128B
        int id = tid + i * 128;
        int r = id >> 3, cb = (id & 7) * 16;
        uint32_t off = (uint32_t)(r * 128 + cb); off ^= (off >> 3) & 0x70;
        cp16(ws + off, Wb + (size_t)r * rb + cb);
    }
    CP_COMMIT();
}

template <int OUT_MODE>
__global__ __launch_bounds__(128, 2)
void gemm_kernel(const __half* __restrict__ A, const __half* __restrict__ W,
                 const float* __restrict__ bias, float* __restrict__ outF,
                 __half* __restrict__ outS, int Ntot, int K)
{
    extern __shared__ char smem[];
    const uint32_t sb = smem_to_u32(smem);
    const int tid = threadIdx.x, wid = tid >> 5, lane = tid & 31;
    const int wm = wid >> 1, wn = wid & 1;           // 2 x 2 warps
    const int m0 = blockIdx.y * 128, n0 = blockIdx.x * 128;
    const int NC = K / 64;

    float acc[4][8][4];                              // warp tile 64x64
#pragma unroll
    for (int i = 0; i < 4; i++)
#pragma unroll
        for (int j = 0; j < 8; j++)
#pragma unroll
            for (int q = 0; q < 4; q++) acc[i][j][q] = 0.0f;

    // A ldsm4: lane q = lane>>3 -> (m-half, k-half)
    const int aq   = lane >> 3;
    const int ari  = lane & 7;
    const int arow = wm * 64 + (aq & 1) * 8 + ari;   // + ma*16
    const int akc  = aq >> 1;
    // B ldsm4: lanes 0-15 -> n-atom 2p (k0,k1), lanes 16-31 -> n-atom 2p+1
    const int bna2 = lane >> 4;
    const int bq   = (lane >> 3) & 1;
    const int bri  = lane & 7;
    const int brow = wn * 64 + bna2 * 8 + bri;       // + pair*16

    load_ab(A, W, K, sb, tid, m0, n0, 0, 0);
    load_ab(A, W, K, sb, tid, m0, n0, 1, 1);

    for (int c = 0; c < NC; c++) {
        if (c + 1 == NC) { CP_WAIT0(); } else { CP_WAIT1(); }
        __syncthreads();
        if (c + 2 < NC) load_ab(A, W, K, sb, tid, m0, n0, c + 2, (c + 2) % 3);

        const int s = c % 3;
        const uint32_t as = sb + s * STAGE_B;
        const uint32_t ws = as + 16384;
#pragma unroll
        for (int ks = 0; ks < 4; ks++) {
            const int kc = ks * 2;
            uint32_t bh[16];                          // frag na: {bh[2na], bh[2na+1]}
            const uint32_t bsw = ((uint32_t)((kc + bq) ^ bri)) << 4;
#pragma unroll
            for (int p = 0; p < 4; p++)
                ldsm4(&bh[4 * p], ws + (brow + p * 16) * 128 + bsw);
            const uint32_t asw = ((uint32_t)((kc + akc) ^ ari)) << 4;
#pragma unroll
            for (int ma = 0; ma < 4; ma++) {
                uint32_t ah[4];
                ldsm4(ah, as + (arow + ma * 16) * 128 + asw);
#pragma unroll
                for (int na = 0; na < 8; na++)
                    mma16816(acc[ma][na], ah, &bh[2 * na]);
            }
        }
    }

    // epilogue
    const int lrow = lane >> 2;
    const int lcol = (lane & 3) * 2;
#pragma unroll
    for (int ma = 0; ma < 4; ma++) {
        const int r0 = m0 + wm * 64 + ma * 16 + lrow;
#pragma unroll
        for (int na = 0; na < 8; na++) {
            const int c0 = n0 + wn * 64 + na * 8 + lcol;
            float v0 = acc[ma][na][0] + bias[c0];
            float v1 = acc[ma][na][1] + bias[c0 + 1];
            float v2 = acc[ma][na][2] + bias[c0];
            float v3 = acc[ma][na][3] + bias[c0 + 1];
            if (OUT_MODE == 0) {
                *(float2*)(outF + (size_t)r0 * Ntot + c0)     = make_float2(v0, v1);
                *(float2*)(outF + (size_t)(r0+8) * Ntot + c0) = make_float2(v2, v3);
            } else {
                v0 = gelu_exact(v0); v1 = gelu_exact(v1);
                v2 = gelu_exact(v2); v3 = gelu_exact(v3);
                *(__half2*)(outS + (size_t)r0 * Ntot + c0) =
                    __half2{__float2half_rn(v0), __float2half_rn(v1)};
                *(__half2*)(outS + (size_t)(r0+8) * Ntot + c0) =
                    __half2{__float2half_rn(v2), __float2half_rn(v3)};
            }
        }
    }
}

// ===========================================================================
// Local causal attention (fp32 in, fp16 out)
// ===========================================================================
__global__ __launch_bounds__(256)
void attn_kernel(const float* __restrict__ qkv, __half* __restrict__ attns)
{
    const int w    = (blockIdx.x * blockDim.x + threadIdx.x) >> 5;
    const int lane = threadIdx.x & 31;
    if (w >= MTOK * HEADS) return;
    const int m = w / HEADS, h = w - m * HEADS, s = m & (SEQ - 1);

    const float* qp = qkv + (size_t)m * (3 * DIMX) + h * HD;
    const float qa = qp[lane], qb = qp[lane + 32];
    const int jlo = (s >= WIN - 1) ? (s - (WIN - 1)) : 0;
    const int cnt = s - jlo + 1;
    const int mlo = m - (s - jlo);

    float sc[WIN];
#pragma unroll
    for (int t = 0; t < WIN; t++) {
        sc[t] = -3.0e38f;
        if (t < cnt) {
            const float* kp = qkv + (size_t)(mlo + t) * (3 * DIMX) + DIMX + h * HD;
            float d = qa * kp[lane] + qb * kp[lane + 32];
#pragma unroll
            for (int o = 16; o > 0; o >>= 1) d += __shfl_xor_sync(0xffffffffu, d, o);
            sc[t] = d * 0.125f;
        }
    }
    float mx = sc[0];
#pragma unroll
    for (int t = 1; t < WIN; t++) mx = fmaxf(mx, sc[t]);
    float p[WIN], sum = 0.0f;
#pragma unroll
    for (int t = 0; t < WIN; t++) { p[t] = (t < cnt) ? __expf(sc[t] - mx) : 0.0f; sum += p[t]; }
    const float inv = 1.0f / sum;

    float oa = 0.0f, ob = 0.0f;
#pragma unroll
    for (int t = 0; t < WIN; t++) {
        if (t < cnt) {
            const float* vp = qkv + (size_t)(mlo + t) * (3 * DIMX) + 2 * DIMX + h * HD;
            oa = fmaf(p[t], vp[lane], oa);
            ob = fmaf(p[t], vp[lane + 32], ob);
        }
    }
    const size_t base = (size_t)m * DIMX + h * HD;
    attns[base + lane]      = __float2half_rn(oa * inv);
    attns[base + lane + 32] = __float2half_rn(ob * inv);
}

// ===========================================================================
// Residual + LayerNorm, float4-vectorized (optionally emit fp16 cast)
// ===========================================================================
template <int CAST>
__global__ __launch_bounds__(256)
void ln_residual_kernel(const float* __restrict__ A, const float* __restrict__ Bv,
                        const float* __restrict__ g, const float* __restrict__ beta,
                        float* __restrict__ out, __half* __restrict__ outs)
{
    const int m = blockIdx.x, tid = threadIdx.x;
    const float4* a4 = (const float4*)(A  + (size_t)m * DIMX);
    const float4* b4 = (const float4*)(Bv + (size_t)m * DIMX);

    float4 av = a4[tid], bv = b4[tid];
    float4 v = make_float4(av.x + bv.x, av.y + bv.y, av.z + bv.z, av.w + bv.w);
    float s  = v.x + v.y + v.z + v.w;
    float s2 = v.x*v.x + v.y*v.y + v.z*v.z + v.w*v.w;
#pragma unroll
    for (int o = 16; o > 0; o >>= 1) {
        s  += __shfl_xor_sync(0xffffffffu, s,  o);
        s2 += __shfl_xor_sync(0xffffffffu, s2, o);
    }
    __shared__ float shs[8], shs2[8], shm, shr;
    const int wid = tid >> 5, lane = tid & 31;
    if (lane == 0) { shs[wid] = s; shs2[wid] = s2; }
    __syncthreads();
    if (tid == 0) {
        float S = 0.0f, S2 = 0.0f;
#pragma unroll
        for (int i = 0; i < 8; i++) { S += shs[i]; S2 += shs2[i]; }
        float mean = S * (1.0f / DIMX);
        shm = mean;
        shr = rsqrtf(S2 * (1.0f / DIMX) - mean * mean + EPSLN);
    }
    __syncthreads();
    const float mean = shm, rstd = shr;
    float4 gv = ((const float4*)g)[tid];
    float4 be = ((const float4*)beta)[tid];
    float4 y;
    y.x = (v.x - mean) * rstd * gv.x + be.x;
    y.y = (v.y - mean) * rstd * gv.y + be.y;
    y.z = (v.z - mean) * rstd * gv.z + be.z;
    y.w = (v.w - mean) * rstd * gv.w + be.w;
    ((float4*)(out + (size_t)m * DIMX))[tid] = y;
    if (CAST) {
        __half2* o2 = (__half2*)(outs + (size_t)m * DIMX + tid * 4);
        o2[0] = __half2{__float2half_rn(y.x), __float2half_rn(y.y)};
        o2[1] = __half2{__float2half_rn(y.z), __float2half_rn(y.w)};
    }
}

// ===========================================================================
// kernel_launch
// ===========================================================================
extern "C" void kernel_launch(void* const* d_in, const int* in_sizes, int n_in,
                              void* d_out, int out_size)
{
    const float* x     = (const float*)d_in[0];
    const float* w_in  = (const float*)d_in[1];
    const float* b_in  = (const float*)d_in[2];
    const float* w_out = (const float*)d_in[3];
    const float* b_out = (const float*)d_in[4];
    const float* ln1_g = (const float*)d_in[5];
    const float* ln1_b = (const float*)d_in[6];
    const float* ln2_g = (const float*)d_in[7];
    const float* ln2_b = (const float*)d_in[8];
    const float* w1    = (const float*)d_in[9];
    const float* b1    = (const float*)d_in[10];
    const float* w2    = (const float*)d_in[11];
    const float* b2    = (const float*)d_in[12];
    float* out = (float*)d_out;

    float *qkv, *attnout, *x1, *mlp;
    __half *xs, *attns, *x1s, *hs, *wins, *wouts, *w1s, *w2s;
    cudaGetSymbolAddress((void**)&qkv,     g_qkv);
    cudaGetSymbolAddress((void**)&attnout, g_attnout);
    cudaGetSymbolAddress((void**)&x1,      g_x1);
    cudaGetSymbolAddress((void**)&mlp,     g_mlp);
    cudaGetSymbolAddress((void**)&xs,      g_xs);
    cudaGetSymbolAddress((void**)&attns,   g_attns);
    cudaGetSymbolAddress((void**)&x1s,     g_x1s);
    cudaGetSymbolAddress((void**)&hs,      g_hs);
    cudaGetSymbolAddress((void**)&wins,    g_wins);
    cudaGetSymbolAddress((void**)&wouts,   g_wouts);
    cudaGetSymbolAddress((void**)&w1s,     g_w1s);
    cudaGetSymbolAddress((void**)&w2s,     g_w2s);

    cudaFuncSetAttribute(gemm_kernel<0>, cudaFuncAttributeMaxDynamicSharedMemorySize, GEMM_SMEM);
    cudaFuncSetAttribute(gemm_kernel<1>, cudaFuncAttributeMaxDynamicSharedMemorySize, GEMM_SMEM);

    // 0. all fp32 -> fp16 casts in one launch
    cast_all_kernel<<<8192, 256>>>(x, w_in, w_out, w1, w2, xs, wins, wouts, w1s, w2s);

    // 1. qkv = x @ w_in^T + b_in           [4096, 3072], K=1024
    gemm_kernel<0><<<dim3(24, 32), 128, GEMM_SMEM>>>(xs, wins, b_in, qkv, nullptr, 3072, 1024);
    // 2. attention -> fp16
    attn_kernel<<<(MTOK * HEADS * 32) / 256, 256>>>(qkv, attns);
    // 3. attnout = attn @ w_out^T + b_out  [4096, 1024], K=1024
    gemm_kernel<0><<<dim3(8, 32), 128, GEMM_SMEM>>>(attns, wouts, b_out, attnout, nullptr, 1024, 1024);
    // 4. x1 = LN1(x + attnout), + fp16 cast
    ln_residual_kernel<1><<<MTOK, 256>>>(x, attnout, ln1_g, ln1_b, x1, x1s);
    // 5. h = gelu(x1 @ w1^T + b1) -> fp16  [4096, 4096], K=1024
    gemm_kernel<1><<<dim3(32, 32), 128, GEMM_SMEM>>>(x1s, w1s, b1, nullptr, hs, 4096, 1024);
    // 6. mlp = h @ w2^T + b2               [4096, 1024], K=4096
    gemm_kernel<0><<<dim3(8, 32), 128, GEMM_SMEM>>>(hs, w2s, b2, mlp, nullptr, 1024, 4096);
    // 7. out = LN2(x1 + mlp)
    ln_residual_kernel<0><<<MTOK, 256>>>(x1, mlp, ln2_g, ln2_b, out, nullptr);

    (void)in_sizes; (void)n_in; (void)out_size;
}